// round 3
// baseline (speedup 1.0000x reference)
#include <cuda_runtime.h>
#include <cstddef>

#define Bx   64
#define Sx   512
#define Dx   256
#define Hx   512
#define Gx   2048   // 4*H
#define OUTx 128

// ---------------- scratch (static device allocations are the allowed path) ---
__device__ float    g_xg[(size_t)Sx * Bx * Gx];   // 256 MB: gate preactivations [s][b][g]
__device__ float    g_h1[(size_t)Sx * Bx * Hx];   //  64 MB: layer-0 hidden history [s][b][j]
__device__ float    g_hT[Hx * Bx];                // current hidden, TRANSPOSED [j][b]
__device__ unsigned g_bar[2];                     // grid-barrier counters (one per scan launch)

// ---------------- init: zero barrier counters (runs every replay) ------------
__global__ void init_kernel() {
    if (threadIdx.x < 2) g_bar[threadIdx.x] = 0u;
}

// ---------------- big GEMM: C[m][n] = sum_k A[m][k]*W[n][k] + b1[n]+b2[n] -----
// M = S*B = 32768 (m -> (s,b)), N = 2048, K = 256 or 512.
// mode 0: A is x[b][s][k]  (row m0+lm -> b=lm, s=blockIdx.y)
// mode 1: A is h1[m][k] contiguous (row stride K)
__global__ void gemm_xg_kernel(const float* __restrict__ A, const float* __restrict__ W,
                               const float* __restrict__ bias1, const float* __restrict__ bias2,
                               float* __restrict__ C, int K, int mode)
{
    __shared__ float As[32][68];
    __shared__ float Bs[32][68];

    const int tid = threadIdx.x;          // 256 threads
    const int m0  = blockIdx.y * 64;
    const int n0  = blockIdx.x * 64;
    const int tx  = tid & 15;             // n quad
    const int ty  = tid >> 4;             // m quad
    const int lm  = tid >> 2;             // loader row 0..63
    const int kq0 = tid & 3;              // loader k-quad base

    const float* arow = (mode == 0)
        ? (A + (size_t)lm * (Sx * Dx) + (size_t)blockIdx.y * Dx)
        : (A + (size_t)(m0 + lm) * K);
    const float* wrow = W + (size_t)(n0 + lm) * K;

    float acc[4][4];
#pragma unroll
    for (int i = 0; i < 4; ++i)
#pragma unroll
        for (int j = 0; j < 4; ++j) acc[i][j] = 0.f;

    for (int k0 = 0; k0 < K; k0 += 32) {
        __syncthreads();
#pragma unroll
        for (int p = 0; p < 2; ++p) {
            int kq = kq0 + 4 * p;
            float4 a = *(const float4*)(arow + k0 + kq * 4);
            float4 w = *(const float4*)(wrow + k0 + kq * 4);
            As[kq*4+0][lm] = a.x; As[kq*4+1][lm] = a.y;
            As[kq*4+2][lm] = a.z; As[kq*4+3][lm] = a.w;
            Bs[kq*4+0][lm] = w.x; Bs[kq*4+1][lm] = w.y;
            Bs[kq*4+2][lm] = w.z; Bs[kq*4+3][lm] = w.w;
        }
        __syncthreads();
#pragma unroll
        for (int k = 0; k < 32; ++k) {
            float4 av = *(const float4*)&As[k][ty * 4];
            float4 bv = *(const float4*)&Bs[k][tx * 4];
            acc[0][0] += av.x * bv.x; acc[0][1] += av.x * bv.y;
            acc[0][2] += av.x * bv.z; acc[0][3] += av.x * bv.w;
            acc[1][0] += av.y * bv.x; acc[1][1] += av.y * bv.y;
            acc[1][2] += av.y * bv.z; acc[1][3] += av.y * bv.w;
            acc[2][0] += av.z * bv.x; acc[2][1] += av.z * bv.y;
            acc[2][2] += av.z * bv.z; acc[2][3] += av.z * bv.w;
            acc[3][0] += av.w * bv.x; acc[3][1] += av.w * bv.y;
            acc[3][2] += av.w * bv.z; acc[3][3] += av.w * bv.w;
        }
    }

    float4 bj;
    bj.x = bias1[n0 + tx*4 + 0] + bias2[n0 + tx*4 + 0];
    bj.y = bias1[n0 + tx*4 + 1] + bias2[n0 + tx*4 + 1];
    bj.z = bias1[n0 + tx*4 + 2] + bias2[n0 + tx*4 + 2];
    bj.w = bias1[n0 + tx*4 + 3] + bias2[n0 + tx*4 + 3];
#pragma unroll
    for (int i = 0; i < 4; ++i) {
        float4 o;
        o.x = acc[i][0] + bj.x; o.y = acc[i][1] + bj.y;
        o.z = acc[i][2] + bj.z; o.w = acc[i][3] + bj.w;
        *(float4*)(C + (size_t)(m0 + ty*4 + i) * Gx + n0 + tx*4) = o;
    }
}

// ---------------- persistent LSTM scan --------------------------------------
// grid = 128 CTAs (one per 4-hidden-unit block), block = 128 threads.
// Each CTA computes, per step, the 16 gate rows {g*H + u0 + u : g 0..3, u 0..3}
// for all 64 batches. K=512 is split across the two warp-pairs.
// Gate row local index r = g*4 + u.
#define SCAN_SMEM_FLOATS (Hx*16 + Hx*Bx + 16*68 + 16*64 + 4*64)
#define SCAN_SMEM_BYTES  (SCAN_SMEM_FLOATS * 4)

__device__ __forceinline__ float sigf(float x) { return 1.f / (1.f + __expf(-x)); }

__global__ void __launch_bounds__(128, 1) lstm_scan_kernel(
    const float* __restrict__ xg,    // [S][B][G] gate preactivations (with biases)
    const float* __restrict__ Whh,   // [G][H]
    float* __restrict__ hT,          // [H][B] current hidden (transposed)
    float* __restrict__ hist,        // [S][B][H] or nullptr
    int barIdx)
{
    extern __shared__ float smf[];
    float* Wt  = smf;                 // [512][16] transposed W tile (resident)
    float* hs  = Wt + Hx * 16;        // [512][64] h transposed
    float* gsm = hs + Hx * Bx;        // [16][68]  gates exchange
    float* psm = gsm + 16 * 68;       // [16][64]  K-split partials
    float* csm = psm + 16 * 64;       // [4][64]   cell state (persistent in smem)

    const int tid = threadIdx.x;
    const int cta = blockIdx.x;
    const int u0  = cta * 4;
    unsigned* bar = &g_bar[barIdx];
    const unsigned nctas = gridDim.x;

    // load W tile transposed: Wt[k][r], r = g*4+u -> global row g*H + u0 + u
    {
        int r  = tid & 15;
        int kc = tid >> 4;                       // 0..7 -> k range [kc*64, kc*64+64)
        int g  = r >> 2, u = r & 3;
        const float* wrow = Whh + (size_t)(g * Hx + u0 + u) * Hx;
        for (int k = kc * 64; k < kc * 64 + 64; k += 4) {
            float4 w = *(const float4*)(wrow + k);
            Wt[(k+0)*16 + r] = w.x;
            Wt[(k+1)*16 + r] = w.y;
            Wt[(k+2)*16 + r] = w.z;
            Wt[(k+3)*16 + r] = w.w;
        }
    }
    for (int i = tid; i < 4 * 64; i += 128) csm[i] = 0.f;
    __syncthreads();

    const int half = tid >> 6;      // K-split half
    const int lt   = tid & 63;
    const int bq   = lt & 15;       // batch quad
    const int rq   = lt >> 4;       // gate index (rows rq*4 .. rq*4+3)
    const int b0   = bq * 4;

    for (int s = 0; s < Sx; ++s) {
        float acc[4][4];
#pragma unroll
        for (int i = 0; i < 4; ++i)
#pragma unroll
            for (int j = 0; j < 4; ++j) acc[i][j] = 0.f;

        if (s > 0) {
            // reload h (written by other SMs last step) -> smem, L2 path
            const float4* src = (const float4*)hT;
            float4*       dst = (float4*)hs;
#pragma unroll 8
            for (int i = 0; i < 64; ++i)
                dst[tid + i * 128] = __ldcg(src + tid + i * 128);
            __syncthreads();

            const float* hp = hs + (size_t)(half * 256) * 64 + b0;
            const float* wp = Wt + (size_t)(half * 256) * 16 + rq * 4;
#pragma unroll 4
            for (int k = 0; k < 256; ++k) {
                float4 hv = *(const float4*)(hp + k * 64);
                float4 wv = *(const float4*)(wp + k * 16);
                acc[0][0] += hv.x * wv.x; acc[0][1] += hv.x * wv.y;
                acc[0][2] += hv.x * wv.z; acc[0][3] += hv.x * wv.w;
                acc[1][0] += hv.y * wv.x; acc[1][1] += hv.y * wv.y;
                acc[1][2] += hv.y * wv.z; acc[1][3] += hv.y * wv.w;
                acc[2][0] += hv.z * wv.x; acc[2][1] += hv.z * wv.y;
                acc[2][2] += hv.z * wv.z; acc[2][3] += hv.z * wv.w;
                acc[3][0] += hv.w * wv.x; acc[3][1] += hv.w * wv.y;
                acc[3][2] += hv.w * wv.z; acc[3][3] += hv.w * wv.w;
            }
        }
        __syncthreads();
        if (half == 1) {
#pragma unroll
            for (int j = 0; j < 4; ++j) {
                float4 v = make_float4(acc[0][j], acc[1][j], acc[2][j], acc[3][j]);
                *(float4*)&psm[(rq * 4 + j) * 64 + b0] = v;
            }
        }
        __syncthreads();
        if (half == 0) {
#pragma unroll
            for (int i = 0; i < 4; ++i) {
                float4 xv = *(const float4*)(xg + (size_t)(s * Bx + b0 + i) * Gx + rq * Hx + u0);
                acc[i][0] += xv.x; acc[i][1] += xv.y;
                acc[i][2] += xv.z; acc[i][3] += xv.w;
            }
#pragma unroll
            for (int j = 0; j < 4; ++j) {
                float4 p = *(const float4*)&psm[(rq * 4 + j) * 64 + b0];
                float4 v = make_float4(acc[0][j] + p.x, acc[1][j] + p.y,
                                       acc[2][j] + p.z, acc[3][j] + p.w);
                *(float4*)&gsm[(rq * 4 + j) * 68 + b0] = v;
            }
        }
        __syncthreads();
        if (tid < 64) {
            int uu = tid >> 4;
            int bb = (tid & 15) * 4;
            float4 iv = *(const float4*)&gsm[( 0 + uu) * 68 + bb];
            float4 fv = *(const float4*)&gsm[( 4 + uu) * 68 + bb];
            float4 gv = *(const float4*)&gsm[( 8 + uu) * 68 + bb];
            float4 ov = *(const float4*)&gsm[(12 + uu) * 68 + bb];
            float4 cv = *(float4*)&csm[uu * 64 + bb];
            float4 hv4;
#define LSTM_ELEM(X) { \
            float ci = sigf(iv.X); float cf = sigf(fv.X); \
            float cg = tanhf(gv.X); float co = sigf(ov.X); \
            cv.X = cf * cv.X + ci * cg; \
            hv4.X = co * tanhf(cv.X); }
            LSTM_ELEM(x) LSTM_ELEM(y) LSTM_ELEM(z) LSTM_ELEM(w)
#undef LSTM_ELEM
            *(float4*)&csm[uu * 64 + bb] = cv;
            *(float4*)(hT + (size_t)(u0 + uu) * Bx + bb) = hv4;
            if (hist) {
                int j = u0 + uu;
                hist[(size_t)(s * Bx + bb + 0) * Hx + j] = hv4.x;
                hist[(size_t)(s * Bx + bb + 1) * Hx + j] = hv4.y;
                hist[(size_t)(s * Bx + bb + 2) * Hx + j] = hv4.z;
                hist[(size_t)(s * Bx + bb + 3) * Hx + j] = hv4.w;
            }
        }
        // ---- grid barrier ----
        __syncthreads();
        if (tid == 0) {
            __threadfence();
            atomicAdd(bar, 1u);
            unsigned target = nctas * (unsigned)(s + 1);
            while (*((volatile unsigned*)bar) < target) {}
            __threadfence();
        }
        __syncthreads();
    }
}

// ---------------- final FC ---------------------------------------------------
__global__ void fc_kernel(const float* __restrict__ hT, const float* __restrict__ fw,
                          const float* __restrict__ fb, float* __restrict__ out)
{
    __shared__ float hb[Hx];
    int b = blockIdx.x;
    int o = threadIdx.x;          // 128 threads
    for (int j = threadIdx.x; j < Hx; j += OUTx) hb[j] = hT[j * Bx + b];
    __syncthreads();
    float acc = fb[o];
    const float* wr = fw + (size_t)o * Hx;
#pragma unroll 4
    for (int j = 0; j < Hx; j += 4) {
        float4 w = *(const float4*)(wr + j);
        float4 h = *(const float4*)(hb + j);
        acc += w.x * h.x + w.y * h.y + w.z * h.z + w.w * h.w;
    }
    out[b * OUTx + o] = acc;
}

// ---------------- launch ------------------------------------------------------
extern "C" void kernel_launch(void* const* d_in, const int* in_sizes, int n_in,
                              void* d_out, int out_size)
{
    const float* x    = (const float*)d_in[0];
    const float* Wih0 = (const float*)d_in[1];
    const float* Whh0 = (const float*)d_in[2];
    const float* bih0 = (const float*)d_in[3];
    const float* bhh0 = (const float*)d_in[4];
    const float* Wih1 = (const float*)d_in[5];
    const float* Whh1 = (const float*)d_in[6];
    const float* bih1 = (const float*)d_in[7];
    const float* bhh1 = (const float*)d_in[8];
    const float* fcw  = (const float*)d_in[9];
    const float* fcb  = (const float*)d_in[10];
    float* out = (float*)d_out;

    cudaFuncSetAttribute((const void*)lstm_scan_kernel,
                         cudaFuncAttributeMaxDynamicSharedMemorySize, SCAN_SMEM_BYTES);

    void *xg_p, *h1_p, *hT_p;
    cudaGetSymbolAddress(&xg_p, g_xg);
    cudaGetSymbolAddress(&h1_p, g_h1);
    cudaGetSymbolAddress(&hT_p, g_hT);

    init_kernel<<<1, 32>>>();

    dim3 ggrid(Gx / 64, (Sx * Bx) / 64);   // (32, 512)
    // layer 0 input GEMM: xg0 = x @ W_ih0^T + (b_ih0 + b_hh0)
    gemm_xg_kernel<<<ggrid, 256>>>(x, Wih0, bih0, bhh0, (float*)xg_p, Dx, 0);
    // layer 0 scan (writes full h history)
    lstm_scan_kernel<<<128, 128, SCAN_SMEM_BYTES>>>((const float*)xg_p, Whh0,
                                                    (float*)hT_p, (float*)h1_p, 0);
    // layer 1 input GEMM: xg1 = h1 @ W_ih1^T + (b_ih1 + b_hh1)
    gemm_xg_kernel<<<ggrid, 256>>>((const float*)h1_p, Wih1, bih1, bhh1,
                                   (float*)xg_p, Hx, 1);
    // layer 1 scan (only final h needed)
    lstm_scan_kernel<<<128, 128, SCAN_SMEM_BYTES>>>((const float*)xg_p, Whh1,
                                                    (float*)hT_p, nullptr, 1);
    // final FC on last hidden state
    fc_kernel<<<Bx, OUTx>>>((const float*)hT_p, fcw, fcb, out);
}

// round 4
// speedup vs baseline: 1.0001x; 1.0001x over previous
#include <cuda_runtime.h>
#include <cstddef>

#define Bx   64
#define Sx   512
#define Dx   256
#define Hx   512
#define Gx   2048   // 4*H
#define OUTx 128

// ---------------- scratch (static device allocations are the allowed path) ---
__device__ float    g_xg[(size_t)Sx * Bx * Gx];   // 256 MB: gate preactivations [s][b][g]
__device__ float    g_h1[(size_t)Sx * Bx * Hx];   //  64 MB: layer-0 hidden history [s][b][j]
__device__ float    g_hT[Hx * Bx];                // current hidden, TRANSPOSED [j][b]
__device__ unsigned g_bar[2];                     // grid-barrier counters (one per scan launch)

// ---------------- init: zero barrier counters (runs every replay) ------------
__global__ void init_kernel() {
    if (threadIdx.x < 2) g_bar[threadIdx.x] = 0u;
}

// ---------------- big GEMM: C[m][n] = sum_k A[m][k]*W[n][k] + b1[n]+b2[n] -----
// M = S*B = 32768 (m -> (s,b)), N = 2048, K = 256 or 512.
// mode 0: A is x[b][s][k]  (row m0+lm -> b=lm, s=blockIdx.y)
// mode 1: A is h1[m][k] contiguous (row stride K)
__global__ void gemm_xg_kernel(const float* __restrict__ A, const float* __restrict__ W,
                               const float* __restrict__ bias1, const float* __restrict__ bias2,
                               float* __restrict__ C, int K, int mode)
{
    __shared__ float As[32][68];
    __shared__ float Bs[32][68];

    const int tid = threadIdx.x;          // 256 threads
    const int m0  = blockIdx.y * 64;
    const int n0  = blockIdx.x * 64;
    const int tx  = tid & 15;             // n quad
    const int ty  = tid >> 4;             // m quad
    const int lm  = tid >> 2;             // loader row 0..63
    const int kq0 = tid & 3;              // loader k-quad base

    const float* arow = (mode == 0)
        ? (A + (size_t)lm * (Sx * Dx) + (size_t)blockIdx.y * Dx)
        : (A + (size_t)(m0 + lm) * K);
    const float* wrow = W + (size_t)(n0 + lm) * K;

    float acc[4][4];
#pragma unroll
    for (int i = 0; i < 4; ++i)
#pragma unroll
        for (int j = 0; j < 4; ++j) acc[i][j] = 0.f;

    for (int k0 = 0; k0 < K; k0 += 32) {
        __syncthreads();
#pragma unroll
        for (int p = 0; p < 2; ++p) {
            int kq = kq0 + 4 * p;
            float4 a = *(const float4*)(arow + k0 + kq * 4);
            float4 w = *(const float4*)(wrow + k0 + kq * 4);
            As[kq*4+0][lm] = a.x; As[kq*4+1][lm] = a.y;
            As[kq*4+2][lm] = a.z; As[kq*4+3][lm] = a.w;
            Bs[kq*4+0][lm] = w.x; Bs[kq*4+1][lm] = w.y;
            Bs[kq*4+2][lm] = w.z; Bs[kq*4+3][lm] = w.w;
        }
        __syncthreads();
#pragma unroll
        for (int k = 0; k < 32; ++k) {
            float4 av = *(const float4*)&As[k][ty * 4];
            float4 bv = *(const float4*)&Bs[k][tx * 4];
            acc[0][0] += av.x * bv.x; acc[0][1] += av.x * bv.y;
            acc[0][2] += av.x * bv.z; acc[0][3] += av.x * bv.w;
            acc[1][0] += av.y * bv.x; acc[1][1] += av.y * bv.y;
            acc[1][2] += av.y * bv.z; acc[1][3] += av.y * bv.w;
            acc[2][0] += av.z * bv.x; acc[2][1] += av.z * bv.y;
            acc[2][2] += av.z * bv.z; acc[2][3] += av.z * bv.w;
            acc[3][0] += av.w * bv.x; acc[3][1] += av.w * bv.y;
            acc[3][2] += av.w * bv.z; acc[3][3] += av.w * bv.w;
        }
    }

    float4 bj;
    bj.x = bias1[n0 + tx*4 + 0] + bias2[n0 + tx*4 + 0];
    bj.y = bias1[n0 + tx*4 + 1] + bias2[n0 + tx*4 + 1];
    bj.z = bias1[n0 + tx*4 + 2] + bias2[n0 + tx*4 + 2];
    bj.w = bias1[n0 + tx*4 + 3] + bias2[n0 + tx*4 + 3];
#pragma unroll
    for (int i = 0; i < 4; ++i) {
        float4 o;
        o.x = acc[i][0] + bj.x; o.y = acc[i][1] + bj.y;
        o.z = acc[i][2] + bj.z; o.w = acc[i][3] + bj.w;
        *(float4*)(C + (size_t)(m0 + ty*4 + i) * Gx + n0 + tx*4) = o;
    }
}

// ---------------- persistent LSTM scan --------------------------------------
// grid = 128 CTAs (one per 4-hidden-unit block), block = 128 threads.
// Each CTA computes, per step, the 16 gate rows {g*H + u0 + u : g 0..3, u 0..3}
// for all 64 batches. K=512 is split across the two warp-pairs.
// Gate row local index r = g*4 + u.
#define SCAN_SMEM_FLOATS (Hx*16 + Hx*Bx + 16*68 + 16*64 + 4*64)
#define SCAN_SMEM_BYTES  (SCAN_SMEM_FLOATS * 4)

__device__ __forceinline__ float sigf(float x) { return 1.f / (1.f + __expf(-x)); }

__global__ void __launch_bounds__(128, 1) lstm_scan_kernel(
    const float* __restrict__ xg,    // [S][B][G] gate preactivations (with biases)
    const float* __restrict__ Whh,   // [G][H]
    float* __restrict__ hT,          // [H][B] current hidden (transposed)
    float* __restrict__ hist,        // [S][B][H] or nullptr
    int barIdx)
{
    extern __shared__ float smf[];
    float* Wt  = smf;                 // [512][16] transposed W tile (resident)
    float* hs  = Wt + Hx * 16;        // [512][64] h transposed
    float* gsm = hs + Hx * Bx;        // [16][68]  gates exchange
    float* psm = gsm + 16 * 68;       // [16][64]  K-split partials
    float* csm = psm + 16 * 64;       // [4][64]   cell state (persistent in smem)

    const int tid = threadIdx.x;
    const int cta = blockIdx.x;
    const int u0  = cta * 4;
    unsigned* bar = &g_bar[barIdx];
    const unsigned nctas = gridDim.x;

    // load W tile transposed: Wt[k][r], r = g*4+u -> global row g*H + u0 + u
    {
        int r  = tid & 15;
        int kc = tid >> 4;                       // 0..7 -> k range [kc*64, kc*64+64)
        int g  = r >> 2, u = r & 3;
        const float* wrow = Whh + (size_t)(g * Hx + u0 + u) * Hx;
        for (int k = kc * 64; k < kc * 64 + 64; k += 4) {
            float4 w = *(const float4*)(wrow + k);
            Wt[(k+0)*16 + r] = w.x;
            Wt[(k+1)*16 + r] = w.y;
            Wt[(k+2)*16 + r] = w.z;
            Wt[(k+3)*16 + r] = w.w;
        }
    }
    for (int i = tid; i < 4 * 64; i += 128) csm[i] = 0.f;
    __syncthreads();

    const int half = tid >> 6;      // K-split half
    const int lt   = tid & 63;
    const int bq   = lt & 15;       // batch quad
    const int rq   = lt >> 4;       // gate index (rows rq*4 .. rq*4+3)
    const int b0   = bq * 4;

    for (int s = 0; s < Sx; ++s) {
        float acc[4][4];
#pragma unroll
        for (int i = 0; i < 4; ++i)
#pragma unroll
            for (int j = 0; j < 4; ++j) acc[i][j] = 0.f;

        if (s > 0) {
            // reload h (written by other SMs last step) -> smem, L2 path
            const float4* src = (const float4*)hT;
            float4*       dst = (float4*)hs;
#pragma unroll 8
            for (int i = 0; i < 64; ++i)
                dst[tid + i * 128] = __ldcg(src + tid + i * 128);
            __syncthreads();

            const float* hp = hs + (size_t)(half * 256) * 64 + b0;
            const float* wp = Wt + (size_t)(half * 256) * 16 + rq * 4;
#pragma unroll 4
            for (int k = 0; k < 256; ++k) {
                float4 hv = *(const float4*)(hp + k * 64);
                float4 wv = *(const float4*)(wp + k * 16);
                acc[0][0] += hv.x * wv.x; acc[0][1] += hv.x * wv.y;
                acc[0][2] += hv.x * wv.z; acc[0][3] += hv.x * wv.w;
                acc[1][0] += hv.y * wv.x; acc[1][1] += hv.y * wv.y;
                acc[1][2] += hv.y * wv.z; acc[1][3] += hv.y * wv.w;
                acc[2][0] += hv.z * wv.x; acc[2][1] += hv.z * wv.y;
                acc[2][2] += hv.z * wv.z; acc[2][3] += hv.z * wv.w;
                acc[3][0] += hv.w * wv.x; acc[3][1] += hv.w * wv.y;
                acc[3][2] += hv.w * wv.z; acc[3][3] += hv.w * wv.w;
            }
        }
        __syncthreads();
        if (half == 1) {
#pragma unroll
            for (int j = 0; j < 4; ++j) {
                float4 v = make_float4(acc[0][j], acc[1][j], acc[2][j], acc[3][j]);
                *(float4*)&psm[(rq * 4 + j) * 64 + b0] = v;
            }
        }
        __syncthreads();
        if (half == 0) {
#pragma unroll
            for (int i = 0; i < 4; ++i) {
                float4 xv = *(const float4*)(xg + (size_t)(s * Bx + b0 + i) * Gx + rq * Hx + u0);
                acc[i][0] += xv.x; acc[i][1] += xv.y;
                acc[i][2] += xv.z; acc[i][3] += xv.w;
            }
#pragma unroll
            for (int j = 0; j < 4; ++j) {
                float4 p = *(const float4*)&psm[(rq * 4 + j) * 64 + b0];
                float4 v = make_float4(acc[0][j] + p.x, acc[1][j] + p.y,
                                       acc[2][j] + p.z, acc[3][j] + p.w);
                *(float4*)&gsm[(rq * 4 + j) * 68 + b0] = v;
            }
        }
        __syncthreads();
        if (tid < 64) {
            int uu = tid >> 4;
            int bb = (tid & 15) * 4;
            float4 iv = *(const float4*)&gsm[( 0 + uu) * 68 + bb];
            float4 fv = *(const float4*)&gsm[( 4 + uu) * 68 + bb];
            float4 gv = *(const float4*)&gsm[( 8 + uu) * 68 + bb];
            float4 ov = *(const float4*)&gsm[(12 + uu) * 68 + bb];
            float4 cv = *(float4*)&csm[uu * 64 + bb];
            float4 hv4;
#define LSTM_ELEM(X) { \
            float ci = sigf(iv.X); float cf = sigf(fv.X); \
            float cg = tanhf(gv.X); float co = sigf(ov.X); \
            cv.X = cf * cv.X + ci * cg; \
            hv4.X = co * tanhf(cv.X); }
            LSTM_ELEM(x) LSTM_ELEM(y) LSTM_ELEM(z) LSTM_ELEM(w)
#undef LSTM_ELEM
            *(float4*)&csm[uu * 64 + bb] = cv;
            *(float4*)(hT + (size_t)(u0 + uu) * Bx + bb) = hv4;
            if (hist) {
                int j = u0 + uu;
                hist[(size_t)(s * Bx + bb + 0) * Hx + j] = hv4.x;
                hist[(size_t)(s * Bx + bb + 1) * Hx + j] = hv4.y;
                hist[(size_t)(s * Bx + bb + 2) * Hx + j] = hv4.z;
                hist[(size_t)(s * Bx + bb + 3) * Hx + j] = hv4.w;
            }
        }
        // ---- grid barrier ----
        __syncthreads();
        if (tid == 0) {
            __threadfence();
            atomicAdd(bar, 1u);
            unsigned target = nctas * (unsigned)(s + 1);
            while (*((volatile unsigned*)bar) < target) {}
            __threadfence();
        }
        __syncthreads();
    }
}

// ---------------- final FC ---------------------------------------------------
__global__ void fc_kernel(const float* __restrict__ hT, const float* __restrict__ fw,
                          const float* __restrict__ fb, float* __restrict__ out)
{
    __shared__ float hb[Hx];
    int b = blockIdx.x;
    int o = threadIdx.x;          // 128 threads
    for (int j = threadIdx.x; j < Hx; j += OUTx) hb[j] = hT[j * Bx + b];
    __syncthreads();
    float acc = fb[o];
    const float* wr = fw + (size_t)o * Hx;
#pragma unroll 4
    for (int j = 0; j < Hx; j += 4) {
        float4 w = *(const float4*)(wr + j);
        float4 h = *(const float4*)(hb + j);
        acc += w.x * h.x + w.y * h.y + w.z * h.z + w.w * h.w;
    }
    out[b * OUTx + o] = acc;
}

// ---------------- launch ------------------------------------------------------
extern "C" void kernel_launch(void* const* d_in, const int* in_sizes, int n_in,
                              void* d_out, int out_size)
{
    const float* x    = (const float*)d_in[0];
    const float* Wih0 = (const float*)d_in[1];
    const float* Whh0 = (const float*)d_in[2];
    const float* bih0 = (const float*)d_in[3];
    const float* bhh0 = (const float*)d_in[4];
    const float* Wih1 = (const float*)d_in[5];
    const float* Whh1 = (const float*)d_in[6];
    const float* bih1 = (const float*)d_in[7];
    const float* bhh1 = (const float*)d_in[8];
    const float* fcw  = (const float*)d_in[9];
    const float* fcb  = (const float*)d_in[10];
    float* out = (float*)d_out;

    cudaFuncSetAttribute((const void*)lstm_scan_kernel,
                         cudaFuncAttributeMaxDynamicSharedMemorySize, SCAN_SMEM_BYTES);

    void *xg_p, *h1_p, *hT_p;
    cudaGetSymbolAddress(&xg_p, g_xg);
    cudaGetSymbolAddress(&h1_p, g_h1);
    cudaGetSymbolAddress(&hT_p, g_hT);

    init_kernel<<<1, 32>>>();

    dim3 ggrid(Gx / 64, (Sx * Bx) / 64);   // (32, 512)
    // layer 0 input GEMM: xg0 = x @ W_ih0^T + (b_ih0 + b_hh0)
    gemm_xg_kernel<<<ggrid, 256>>>(x, Wih0, bih0, bhh0, (float*)xg_p, Dx, 0);
    // layer 0 scan (writes full h history)
    lstm_scan_kernel<<<128, 128, SCAN_SMEM_BYTES>>>((const float*)xg_p, Whh0,
                                                    (float*)hT_p, (float*)h1_p, 0);
    // layer 1 input GEMM: xg1 = h1 @ W_ih1^T + (b_ih1 + b_hh1)
    gemm_xg_kernel<<<ggrid, 256>>>((const float*)h1_p, Wih1, bih1, bhh1,
                                   (float*)xg_p, Hx, 1);
    // layer 1 scan (only final h needed)
    lstm_scan_kernel<<<128, 128, SCAN_SMEM_BYTES>>>((const float*)xg_p, Whh1,
                                                    (float*)hT_p, nullptr, 1);
    // final FC on last hidden state
    fc_kernel<<<Bx, OUTx>>>((const float*)hT_p, fcw, fcb, out);
}

// round 5
// speedup vs baseline: 1.0820x; 1.0819x over previous
#include <cuda_runtime.h>
#include <cstddef>

#define Bx   64
#define Sx   512
#define Dx   256
#define Hx   512
#define Gx   2048   // 4*H
#define OUTx 128

// ---------------- scratch (static device allocations are the allowed path) ---
__device__ float    g_xg[(size_t)Sx * Bx * Gx];   // 256 MB: gate preactivations [s][b][g]
__device__ float    g_h1[(size_t)Sx * Bx * Hx];   //  64 MB: layer-0 hidden history [s][b][j]
__device__ float    g_hT[Hx * Bx];                // current hidden, TRANSPOSED [j][b]
__device__ unsigned g_bar[2];                     // grid-barrier counters (one per scan launch)

// ---------------- init: zero barrier counters (runs every replay) ------------
__global__ void init_kernel() {
    if (threadIdx.x < 2) g_bar[threadIdx.x] = 0u;
}

// ---------------- big GEMM: C[m][n] = sum_k A[m][k]*W[n][k] + b1[n]+b2[n] -----
// M = S*B = 32768 (m -> (s,b)), N = 2048, K = 256 or 512.
// mode 0: A is x[b][s][k]  (row m0+lm -> b=lm, s=blockIdx.y)
// mode 1: A is h1[m][k] contiguous (row stride K)
__global__ void gemm_xg_kernel(const float* __restrict__ A, const float* __restrict__ W,
                               const float* __restrict__ bias1, const float* __restrict__ bias2,
                               float* __restrict__ C, int K, int mode)
{
    __shared__ float As[32][68];
    __shared__ float Bs[32][68];

    const int tid = threadIdx.x;          // 256 threads
    const int m0  = blockIdx.y * 64;
    const int n0  = blockIdx.x * 64;
    const int tx  = tid & 15;             // n quad
    const int ty  = tid >> 4;             // m quad
    const int lm  = tid >> 2;             // loader row 0..63
    const int kq0 = tid & 3;              // loader k-quad base

    const float* arow = (mode == 0)
        ? (A + (size_t)lm * (Sx * Dx) + (size_t)blockIdx.y * Dx)
        : (A + (size_t)(m0 + lm) * K);
    const float* wrow = W + (size_t)(n0 + lm) * K;

    float acc[4][4];
#pragma unroll
    for (int i = 0; i < 4; ++i)
#pragma unroll
        for (int j = 0; j < 4; ++j) acc[i][j] = 0.f;

    for (int k0 = 0; k0 < K; k0 += 32) {
        __syncthreads();
#pragma unroll
        for (int p = 0; p < 2; ++p) {
            int kq = kq0 + 4 * p;
            float4 a = *(const float4*)(arow + k0 + kq * 4);
            float4 w = *(const float4*)(wrow + k0 + kq * 4);
            As[kq*4+0][lm] = a.x; As[kq*4+1][lm] = a.y;
            As[kq*4+2][lm] = a.z; As[kq*4+3][lm] = a.w;
            Bs[kq*4+0][lm] = w.x; Bs[kq*4+1][lm] = w.y;
            Bs[kq*4+2][lm] = w.z; Bs[kq*4+3][lm] = w.w;
        }
        __syncthreads();
#pragma unroll
        for (int k = 0; k < 32; ++k) {
            float4 av = *(const float4*)&As[k][ty * 4];
            float4 bv = *(const float4*)&Bs[k][tx * 4];
            acc[0][0] += av.x * bv.x; acc[0][1] += av.x * bv.y;
            acc[0][2] += av.x * bv.z; acc[0][3] += av.x * bv.w;
            acc[1][0] += av.y * bv.x; acc[1][1] += av.y * bv.y;
            acc[1][2] += av.y * bv.z; acc[1][3] += av.y * bv.w;
            acc[2][0] += av.z * bv.x; acc[2][1] += av.z * bv.y;
            acc[2][2] += av.z * bv.z; acc[2][3] += av.z * bv.w;
            acc[3][0] += av.w * bv.x; acc[3][1] += av.w * bv.y;
            acc[3][2] += av.w * bv.z; acc[3][3] += av.w * bv.w;
        }
    }

    float4 bj;
    bj.x = bias1[n0 + tx*4 + 0] + bias2[n0 + tx*4 + 0];
    bj.y = bias1[n0 + tx*4 + 1] + bias2[n0 + tx*4 + 1];
    bj.z = bias1[n0 + tx*4 + 2] + bias2[n0 + tx*4 + 2];
    bj.w = bias1[n0 + tx*4 + 3] + bias2[n0 + tx*4 + 3];
#pragma unroll
    for (int i = 0; i < 4; ++i) {
        float4 o;
        o.x = acc[i][0] + bj.x; o.y = acc[i][1] + bj.y;
        o.z = acc[i][2] + bj.z; o.w = acc[i][3] + bj.w;
        *(float4*)(C + (size_t)(m0 + ty*4 + i) * Gx + n0 + tx*4) = o;
    }
}

// ---------------- persistent LSTM scan --------------------------------------
// grid = 128 CTAs (one per 4-hidden-unit block), block = 256 threads (8 warps).
// Each CTA computes, per step, the 16 gate rows {g*H + u0 + u : g 0..3, u 0..3}
// for all 64 batches. K=512 is split across 4 warp-pair "quarters"; each
// quarter loads only its own 32 KB slab of h (named barrier) so the L2
// broadcast pipelines under FFMA issue, and 2 warps/SMSP hide LDS latency.
#define SCAN_SMEM_FLOATS (Hx*16 + Hx*Bx + 3*16*64 + 16*68 + 4*64)
#define SCAN_SMEM_BYTES  (SCAN_SMEM_FLOATS * 4)

__device__ __forceinline__ float sigf(float x) { return 1.f / (1.f + __expf(-x)); }

__global__ void __launch_bounds__(256, 1) lstm_scan_kernel(
    const float* __restrict__ xg,    // [S][B][G] gate preactivations (with biases)
    const float* __restrict__ Whh,   // [G][H]
    float* __restrict__ hT,          // [H][B] current hidden (transposed)
    float* __restrict__ hist,        // [S][B][H] or nullptr
    int barIdx)
{
    extern __shared__ float smf[];
    float* Wt  = smf;                 // [512][16] transposed W tile (resident)
    float* hs  = Wt + Hx * 16;        // [512][64] h transposed
    float* psm = hs + Hx * Bx;        // [3][16][64] K-split partials (quarters 1..3)
    float* gsm = psm + 3 * 16 * 64;   // [16][68]  gates exchange
    float* csm = gsm + 16 * 68;       // [4][64]   cell state (persistent in smem)

    const int tid = threadIdx.x;
    const int cta = blockIdx.x;
    const int u0  = cta * 4;
    unsigned* bar = &g_bar[barIdx];
    const unsigned nctas = gridDim.x;

    // load W tile transposed: Wt[k][r], r = g*4+u -> global row g*H + u0 + u
    {
        int r  = tid & 15;
        int kc = tid >> 4;                       // 0..15 -> k range [kc*32, kc*32+32)
        int g  = r >> 2, u = r & 3;
        const float* wrow = Whh + (size_t)(g * Hx + u0 + u) * Hx;
        for (int k = kc * 32; k < kc * 32 + 32; k += 4) {
            float4 w = *(const float4*)(wrow + k);
            Wt[(k+0)*16 + r] = w.x;
            Wt[(k+1)*16 + r] = w.y;
            Wt[(k+2)*16 + r] = w.z;
            Wt[(k+3)*16 + r] = w.w;
        }
    }
    if (tid < 4 * 64) csm[tid] = 0.f;
    __syncthreads();

    const int quarter = tid >> 6;   // K-split quarter: k in [128*q, 128*q+128)
    const int lt   = tid & 63;
    const int bq   = lt & 15;       // batch quad
    const int rq   = lt >> 4;       // gate index (rows rq*4 .. rq*4+3)
    const int b0   = bq * 4;
    const int k0   = quarter * 128;

    for (int s = 0; s < Sx; ++s) {
        float acc[4][4];
#pragma unroll
        for (int i = 0; i < 4; ++i)
#pragma unroll
            for (int j = 0; j < 4; ++j) acc[i][j] = 0.f;

        if (s > 0) {
            // each quarter reloads ONLY its own 32 KB slab of h (L2 path),
            // then syncs just its warp-pair and starts computing immediately
            const float4* src = (const float4*)hT + quarter * 2048;
            float4*       dst = (float4*)hs      + quarter * 2048;
#pragma unroll 8
            for (int i = 0; i < 32; ++i)
                dst[lt + i * 64] = __ldcg(src + lt + i * 64);
            asm volatile("bar.sync %0, 64;" :: "r"(quarter + 1) : "memory");

            const float* hp = hs + (size_t)k0 * 64 + b0;
            const float* wp = Wt + (size_t)k0 * 16 + rq * 4;
#pragma unroll 4
            for (int k = 0; k < 128; ++k) {
                float4 hv = *(const float4*)(hp + k * 64);
                float4 wv = *(const float4*)(wp + k * 16);
                acc[0][0] += hv.x * wv.x; acc[0][1] += hv.x * wv.y;
                acc[0][2] += hv.x * wv.z; acc[0][3] += hv.x * wv.w;
                acc[1][0] += hv.y * wv.x; acc[1][1] += hv.y * wv.y;
                acc[1][2] += hv.y * wv.z; acc[1][3] += hv.y * wv.w;
                acc[2][0] += hv.z * wv.x; acc[2][1] += hv.z * wv.y;
                acc[2][2] += hv.z * wv.z; acc[2][3] += hv.z * wv.w;
                acc[3][0] += hv.w * wv.x; acc[3][1] += hv.w * wv.y;
                acc[3][2] += hv.w * wv.z; acc[3][3] += hv.w * wv.w;
            }
        }
        __syncthreads();
        if (quarter != 0) {
            float* pq = psm + (quarter - 1) * (16 * 64);
#pragma unroll
            for (int j = 0; j < 4; ++j) {
                float4 v = make_float4(acc[0][j], acc[1][j], acc[2][j], acc[3][j]);
                *(float4*)&pq[(rq * 4 + j) * 64 + b0] = v;
            }
        }
        __syncthreads();
        if (quarter == 0) {
#pragma unroll
            for (int i = 0; i < 4; ++i) {
                float4 xv = *(const float4*)(xg + (size_t)(s * Bx + b0 + i) * Gx + rq * Hx + u0);
                acc[i][0] += xv.x; acc[i][1] += xv.y;
                acc[i][2] += xv.z; acc[i][3] += xv.w;
            }
#pragma unroll
            for (int j = 0; j < 4; ++j) {
                float4 p0 = *(const float4*)&psm[0 * 1024 + (rq * 4 + j) * 64 + b0];
                float4 p1 = *(const float4*)&psm[1 * 1024 + (rq * 4 + j) * 64 + b0];
                float4 p2 = *(const float4*)&psm[2 * 1024 + (rq * 4 + j) * 64 + b0];
                float4 v = make_float4(acc[0][j] + p0.x + p1.x + p2.x,
                                       acc[1][j] + p0.y + p1.y + p2.y,
                                       acc[2][j] + p0.z + p1.z + p2.z,
                                       acc[3][j] + p0.w + p1.w + p2.w);
                *(float4*)&gsm[(rq * 4 + j) * 68 + b0] = v;
            }
        }
        __syncthreads();
        if (tid < 64) {
            int uu = tid >> 4;
            int bb = (tid & 15) * 4;
            float4 iv = *(const float4*)&gsm[( 0 + uu) * 68 + bb];
            float4 fv = *(const float4*)&gsm[( 4 + uu) * 68 + bb];
            float4 gv = *(const float4*)&gsm[( 8 + uu) * 68 + bb];
            float4 ov = *(const float4*)&gsm[(12 + uu) * 68 + bb];
            float4 cv = *(float4*)&csm[uu * 64 + bb];
            float4 hv4;
#define LSTM_ELEM(X) { \
            float ci = sigf(iv.X); float cf = sigf(fv.X); \
            float cg = tanhf(gv.X); float co = sigf(ov.X); \
            cv.X = cf * cv.X + ci * cg; \
            hv4.X = co * tanhf(cv.X); }
            LSTM_ELEM(x) LSTM_ELEM(y) LSTM_ELEM(z) LSTM_ELEM(w)
#undef LSTM_ELEM
            *(float4*)&csm[uu * 64 + bb] = cv;
            *(float4*)(hT + (size_t)(u0 + uu) * Bx + bb) = hv4;
            if (hist) {
                int j = u0 + uu;
                hist[(size_t)(s * Bx + bb + 0) * Hx + j] = hv4.x;
                hist[(size_t)(s * Bx + bb + 1) * Hx + j] = hv4.y;
                hist[(size_t)(s * Bx + bb + 2) * Hx + j] = hv4.z;
                hist[(size_t)(s * Bx + bb + 3) * Hx + j] = hv4.w;
            }
        }
        // ---- grid barrier ----
        __syncthreads();
        if (tid == 0) {
            __threadfence();
            atomicAdd(bar, 1u);
            unsigned target = nctas * (unsigned)(s + 1);
            while (*((volatile unsigned*)bar) < target) {}
            __threadfence();
        }
        __syncthreads();
    }
}

// ---------------- final FC ---------------------------------------------------
__global__ void fc_kernel(const float* __restrict__ hT, const float* __restrict__ fw,
                          const float* __restrict__ fb, float* __restrict__ out)
{
    __shared__ float hb[Hx];
    int b = blockIdx.x;
    int o = threadIdx.x;          // 128 threads
    for (int j = threadIdx.x; j < Hx; j += OUTx) hb[j] = hT[j * Bx + b];
    __syncthreads();
    float acc = fb[o];
    const float* wr = fw + (size_t)o * Hx;
#pragma unroll 4
    for (int j = 0; j < Hx; j += 4) {
        float4 w = *(const float4*)(wr + j);
        float4 h = *(const float4*)(hb + j);
        acc += w.x * h.x + w.y * h.y + w.z * h.z + w.w * h.w;
    }
    out[b * OUTx + o] = acc;
}

// ---------------- launch ------------------------------------------------------
extern "C" void kernel_launch(void* const* d_in, const int* in_sizes, int n_in,
                              void* d_out, int out_size)
{
    const float* x    = (const float*)d_in[0];
    const float* Wih0 = (const float*)d_in[1];
    const float* Whh0 = (const float*)d_in[2];
    const float* bih0 = (const float*)d_in[3];
    const float* bhh0 = (const float*)d_in[4];
    const float* Wih1 = (const float*)d_in[5];
    const float* Whh1 = (const float*)d_in[6];
    const float* bih1 = (const float*)d_in[7];
    const float* bhh1 = (const float*)d_in[8];
    const float* fcw  = (const float*)d_in[9];
    const float* fcb  = (const float*)d_in[10];
    float* out = (float*)d_out;

    cudaFuncSetAttribute((const void*)lstm_scan_kernel,
                         cudaFuncAttributeMaxDynamicSharedMemorySize, SCAN_SMEM_BYTES);

    void *xg_p, *h1_p, *hT_p;
    cudaGetSymbolAddress(&xg_p, g_xg);
    cudaGetSymbolAddress(&h1_p, g_h1);
    cudaGetSymbolAddress(&hT_p, g_hT);

    init_kernel<<<1, 32>>>();

    dim3 ggrid(Gx / 64, (Sx * Bx) / 64);   // (32, 512)
    // layer 0 input GEMM: xg0 = x @ W_ih0^T + (b_ih0 + b_hh0)
    gemm_xg_kernel<<<ggrid, 256>>>(x, Wih0, bih0, bhh0, (float*)xg_p, Dx, 0);
    // layer 0 scan (writes full h history)
    lstm_scan_kernel<<<128, 256, SCAN_SMEM_BYTES>>>((const float*)xg_p, Whh0,
                                                    (float*)hT_p, (float*)h1_p, 0);
    // layer 1 input GEMM: xg1 = h1 @ W_ih1^T + (b_ih1 + b_hh1)
    gemm_xg_kernel<<<ggrid, 256>>>((const float*)h1_p, Wih1, bih1, bhh1,
                                   (float*)xg_p, Hx, 1);
    // layer 1 scan (only final h needed)
    lstm_scan_kernel<<<128, 256, SCAN_SMEM_BYTES>>>((const float*)xg_p, Whh1,
                                                    (float*)hT_p, nullptr, 1);
    // final FC on last hidden state
    fc_kernel<<<Bx, OUTx>>>((const float*)hT_p, fcw, fcb, out);
}

// round 6
// speedup vs baseline: 1.2262x; 1.1333x over previous
#include <cuda_runtime.h>
#include <cstddef>

#define Bx   64
#define Sx   512
#define Dx   256
#define Hx   512
#define Gx   2048   // 4*H
#define OUTx 128

// ---------------- scratch (static device allocations are the allowed path) ---
__device__ float    g_xg[(size_t)Sx * Bx * Gx];   // 256 MB: gate preactivations [s][b][g]
__device__ float    g_h1[(size_t)Sx * Bx * Hx];   //  64 MB: layer-0 hidden history [s][b][j]
__device__ float    g_hT[Hx * Bx];                // current hidden, TRANSPOSED [j][b]
__device__ unsigned g_bar[2];                     // grid-barrier counters (one per scan launch)

// ---------------- init: zero barrier counters (runs every replay) ------------
__global__ void init_kernel() {
    if (threadIdx.x < 2) g_bar[threadIdx.x] = 0u;
}

// ---------------- big GEMM: C[m][n] = sum_k A[m][k]*W[n][k] + b1[n]+b2[n] -----
// 128x128 tile, 8x8 micro-tile, double-buffered smem, reg-staged LDG.
// M = S*B = 32768 (m -> (s,b)), N = 2048, K = 256 or 512.
// mode 0: A is x[b][s][k]  (row m -> b=m&63, s=m>>6)
// mode 1: A is h1[m][k] contiguous (row stride K)
__global__ void __launch_bounds__(256, 2) gemm_xg_kernel(
    const float* __restrict__ A, const float* __restrict__ W,
    const float* __restrict__ bias1, const float* __restrict__ bias2,
    float* __restrict__ C, int K, int mode)
{
    __shared__ float As[2][8][132];
    __shared__ float Bs[2][8][132];

    const int tid = threadIdx.x;          // 256 threads
    const int m0  = blockIdx.y * 128;
    const int n0  = blockIdx.x * 128;

    // loader mapping: each thread owns one row, one 4-float k-slice
    const int lr = tid >> 1;              // 0..127
    const int lk = (tid & 1) * 4;         // 0 or 4

    const float* aptr;
    if (mode == 0) {
        int m = m0 + lr; int b = m & 63; int s = m >> 6;
        aptr = A + (size_t)b * (Sx * Dx) + (size_t)s * Dx + lk;
    } else {
        aptr = A + (size_t)(m0 + lr) * K + lk;
    }
    const float* wptr = W + (size_t)(n0 + lr) * K + lk;

    const int tx = tid & 15;              // col block (8 cols)
    const int ty = tid >> 4;              // row block (8 rows)

    float acc[8][8];
#pragma unroll
    for (int i = 0; i < 8; ++i)
#pragma unroll
        for (int j = 0; j < 8; ++j) acc[i][j] = 0.f;

    // prologue: tile 0
    {
        float4 a = *(const float4*)aptr;
        float4 w = *(const float4*)wptr;
        As[0][lk+0][lr] = a.x; As[0][lk+1][lr] = a.y;
        As[0][lk+2][lr] = a.z; As[0][lk+3][lr] = a.w;
        Bs[0][lk+0][lr] = w.x; Bs[0][lk+1][lr] = w.y;
        Bs[0][lk+2][lr] = w.z; Bs[0][lk+3][lr] = w.w;
    }
    __syncthreads();

    int buf = 0;
    const int ntiles = K >> 3;
    for (int t = 0; t < ntiles; ++t) {
        float4 an, wn;
        const bool more = (t + 1 < ntiles);
        if (more) {
            an = *(const float4*)(aptr + (t + 1) * 8);
            wn = *(const float4*)(wptr + (t + 1) * 8);
        }
#pragma unroll
        for (int kk = 0; kk < 8; ++kk) {
            float4 a0 = *(const float4*)&As[buf][kk][ty * 8];
            float4 a1 = *(const float4*)&As[buf][kk][ty * 8 + 4];
            float4 b0 = *(const float4*)&Bs[buf][kk][tx * 8];
            float4 b1 = *(const float4*)&Bs[buf][kk][tx * 8 + 4];
            float av[8] = {a0.x, a0.y, a0.z, a0.w, a1.x, a1.y, a1.z, a1.w};
            float bv[8] = {b0.x, b0.y, b0.z, b0.w, b1.x, b1.y, b1.z, b1.w};
#pragma unroll
            for (int i = 0; i < 8; ++i)
#pragma unroll
                for (int j = 0; j < 8; ++j)
                    acc[i][j] = fmaf(av[i], bv[j], acc[i][j]);
        }
        if (more) {
            buf ^= 1;
            As[buf][lk+0][lr] = an.x; As[buf][lk+1][lr] = an.y;
            As[buf][lk+2][lr] = an.z; As[buf][lk+3][lr] = an.w;
            Bs[buf][lk+0][lr] = wn.x; Bs[buf][lk+1][lr] = wn.y;
            Bs[buf][lk+2][lr] = wn.z; Bs[buf][lk+3][lr] = wn.w;
            __syncthreads();
        }
    }

    // epilogue: bias + store
    float4 p1a = *(const float4*)(bias1 + n0 + tx * 8);
    float4 p1b = *(const float4*)(bias1 + n0 + tx * 8 + 4);
    float4 p2a = *(const float4*)(bias2 + n0 + tx * 8);
    float4 p2b = *(const float4*)(bias2 + n0 + tx * 8 + 4);
    float bj[8] = {p1a.x + p2a.x, p1a.y + p2a.y, p1a.z + p2a.z, p1a.w + p2a.w,
                   p1b.x + p2b.x, p1b.y + p2b.y, p1b.z + p2b.z, p1b.w + p2b.w};
#pragma unroll
    for (int i = 0; i < 8; ++i) {
        size_t row = (size_t)(m0 + ty * 8 + i);
        float4 o0, o1;
        o0.x = acc[i][0] + bj[0]; o0.y = acc[i][1] + bj[1];
        o0.z = acc[i][2] + bj[2]; o0.w = acc[i][3] + bj[3];
        o1.x = acc[i][4] + bj[4]; o1.y = acc[i][5] + bj[5];
        o1.z = acc[i][6] + bj[6]; o1.w = acc[i][7] + bj[7];
        *(float4*)(C + row * Gx + n0 + tx * 8)     = o0;
        *(float4*)(C + row * Gx + n0 + tx * 8 + 4) = o1;
    }
}

// ---------------- persistent LSTM scan --------------------------------------
// grid = 128 CTAs (one per 4-hidden-unit block), block = 256 threads (8 warps).
// K=512 split across 4 warp-pair quarters. Each quarter streams its 32 KB slab
// of h in 4 chunks of 32 k, pipelined under the FFMA compute of the previous
// chunk, so the 16 MB/step L2 broadcast hides under the FFMA floor.
#define SCAN_SMEM_FLOATS (Hx*16 + Hx*Bx + 3*16*64 + 16*68 + 4*64)
#define SCAN_SMEM_BYTES  (SCAN_SMEM_FLOATS * 4)

__device__ __forceinline__ float tanhap(float x) {
    float y; asm("tanh.approx.f32 %0, %1;" : "=f"(y) : "f"(x)); return y;
}
__device__ __forceinline__ float sigf(float x) {
    return fmaf(tanhap(x * 0.5f), 0.5f, 0.5f);
}

__global__ void __launch_bounds__(256, 1) lstm_scan_kernel(
    const float* __restrict__ xg,    // [S][B][G] gate preactivations (with biases)
    const float* __restrict__ Whh,   // [G][H]
    float* __restrict__ hT,          // [H][B] current hidden (transposed)
    float* __restrict__ hist,        // [S][B][H] or nullptr
    int barIdx)
{
    extern __shared__ float smf[];
    float* Wt  = smf;                 // [512][16] transposed W tile (resident)
    float* hs  = Wt + Hx * 16;        // [512][64] h transposed
    float* psm = hs + Hx * Bx;        // [3][16][64] K-split partials (quarters 1..3)
    float* gsm = psm + 3 * 16 * 64;   // [16][68]  gates exchange
    float* csm = gsm + 16 * 68;       // [4][64]   cell state (persistent in smem)

    const int tid = threadIdx.x;
    const int cta = blockIdx.x;
    const int u0  = cta * 4;
    unsigned* bar = &g_bar[barIdx];
    const unsigned nctas = gridDim.x;

    // load W tile transposed: Wt[k][r], r = g*4+u -> global row g*H + u0 + u
    {
        int r  = tid & 15;
        int kc = tid >> 4;                       // 0..15 -> k range [kc*32, kc*32+32)
        int g  = r >> 2, u = r & 3;
        const float* wrow = Whh + (size_t)(g * Hx + u0 + u) * Hx;
        for (int k = kc * 32; k < kc * 32 + 32; k += 4) {
            float4 w = *(const float4*)(wrow + k);
            Wt[(k+0)*16 + r] = w.x;
            Wt[(k+1)*16 + r] = w.y;
            Wt[(k+2)*16 + r] = w.z;
            Wt[(k+3)*16 + r] = w.w;
        }
    }
    if (tid < 4 * 64) csm[tid] = 0.f;
    __syncthreads();

    const int quarter = tid >> 6;   // K-split quarter: k in [128*q, 128*q+128)
    const int lt   = tid & 63;
    const int bq   = lt & 15;       // batch quad
    const int rq   = lt >> 4;       // gate index (rows rq*4 .. rq*4+3)
    const int b0   = bq * 4;
    const int k0   = quarter * 128;

    for (int s = 0; s < Sx; ++s) {
        float acc[4][4];
#pragma unroll
        for (int i = 0; i < 4; ++i)
#pragma unroll
            for (int j = 0; j < 4; ++j) acc[i][j] = 0.f;

        // quarter 0 prefetches its xg tail contribution early (hidden latency)
        float4 xv0, xv1, xv2, xv3;
        if (quarter == 0) {
            const float* xb = xg + (size_t)(s * Bx + b0) * Gx + rq * Hx + u0;
            xv0 = __ldcg((const float4*)(xb));
            xv1 = __ldcg((const float4*)(xb + Gx));
            xv2 = __ldcg((const float4*)(xb + 2 * Gx));
            xv3 = __ldcg((const float4*)(xb + 3 * Gx));
        }

        if (s > 0) {
            // stream this quarter's 32 KB h-slab in 4 chunks of 32 k,
            // pipelined: STS(c) -> pair-bar -> LDG(c+1) -> compute(c)
            const float4* srcq = (const float4*)hT + quarter * 2048;
            float4*       dstq = (float4*)hs      + quarter * 2048;
            float4 st[8];
#pragma unroll
            for (int i = 0; i < 8; ++i)
                st[i] = __ldcg(srcq + lt + i * 64);

#pragma unroll
            for (int c = 0; c < 4; ++c) {
#pragma unroll
                for (int i = 0; i < 8; ++i)
                    dstq[c * 512 + lt + i * 64] = st[i];
                asm volatile("bar.sync %0, 64;" :: "r"(quarter + 1) : "memory");
                if (c < 3) {
#pragma unroll
                    for (int i = 0; i < 8; ++i)
                        st[i] = __ldcg(srcq + (c + 1) * 512 + lt + i * 64);
                }
                const float* hp = hs + (size_t)(k0 + 32 * c) * 64 + b0;
                const float* wp = Wt + (size_t)(k0 + 32 * c) * 16 + rq * 4;
#pragma unroll 4
                for (int k = 0; k < 32; ++k) {
                    float4 hv = *(const float4*)(hp + k * 64);
                    float4 wv = *(const float4*)(wp + k * 16);
                    acc[0][0] += hv.x * wv.x; acc[0][1] += hv.x * wv.y;
                    acc[0][2] += hv.x * wv.z; acc[0][3] += hv.x * wv.w;
                    acc[1][0] += hv.y * wv.x; acc[1][1] += hv.y * wv.y;
                    acc[1][2] += hv.y * wv.z; acc[1][3] += hv.y * wv.w;
                    acc[2][0] += hv.z * wv.x; acc[2][1] += hv.z * wv.y;
                    acc[2][2] += hv.z * wv.z; acc[2][3] += hv.z * wv.w;
                    acc[3][0] += hv.w * wv.x; acc[3][1] += hv.w * wv.y;
                    acc[3][2] += hv.w * wv.z; acc[3][3] += hv.w * wv.w;
                }
            }
        }
        __syncthreads();
        if (quarter != 0) {
            float* pq = psm + (quarter - 1) * (16 * 64);
#pragma unroll
            for (int j = 0; j < 4; ++j) {
                float4 v = make_float4(acc[0][j], acc[1][j], acc[2][j], acc[3][j]);
                *(float4*)&pq[(rq * 4 + j) * 64 + b0] = v;
            }
        }
        __syncthreads();
        if (quarter == 0) {
            acc[0][0] += xv0.x; acc[0][1] += xv0.y; acc[0][2] += xv0.z; acc[0][3] += xv0.w;
            acc[1][0] += xv1.x; acc[1][1] += xv1.y; acc[1][2] += xv1.z; acc[1][3] += xv1.w;
            acc[2][0] += xv2.x; acc[2][1] += xv2.y; acc[2][2] += xv2.z; acc[2][3] += xv2.w;
            acc[3][0] += xv3.x; acc[3][1] += xv3.y; acc[3][2] += xv3.z; acc[3][3] += xv3.w;
#pragma unroll
            for (int j = 0; j < 4; ++j) {
                float4 p0 = *(const float4*)&psm[0 * 1024 + (rq * 4 + j) * 64 + b0];
                float4 p1 = *(const float4*)&psm[1 * 1024 + (rq * 4 + j) * 64 + b0];
                float4 p2 = *(const float4*)&psm[2 * 1024 + (rq * 4 + j) * 64 + b0];
                float4 v = make_float4(acc[0][j] + p0.x + p1.x + p2.x,
                                       acc[1][j] + p0.y + p1.y + p2.y,
                                       acc[2][j] + p0.z + p1.z + p2.z,
                                       acc[3][j] + p0.w + p1.w + p2.w);
                *(float4*)&gsm[(rq * 4 + j) * 68 + b0] = v;
            }
        }
        __syncthreads();
        if (tid < 64) {
            int uu = tid >> 4;
            int bb = (tid & 15) * 4;
            float4 iv = *(const float4*)&gsm[( 0 + uu) * 68 + bb];
            float4 fv = *(const float4*)&gsm[( 4 + uu) * 68 + bb];
            float4 gv = *(const float4*)&gsm[( 8 + uu) * 68 + bb];
            float4 ov = *(const float4*)&gsm[(12 + uu) * 68 + bb];
            float4 cv = *(float4*)&csm[uu * 64 + bb];
            float4 hv4;
#define LSTM_ELEM(X) { \
            float ci = sigf(iv.X); float cf = sigf(fv.X); \
            float cg = tanhap(gv.X); float co = sigf(ov.X); \
            cv.X = cf * cv.X + ci * cg; \
            hv4.X = co * tanhap(cv.X); }
            LSTM_ELEM(x) LSTM_ELEM(y) LSTM_ELEM(z) LSTM_ELEM(w)
#undef LSTM_ELEM
            *(float4*)&csm[uu * 64 + bb] = cv;
            *(float4*)(hT + (size_t)(u0 + uu) * Bx + bb) = hv4;
            if (hist) {
                int j = u0 + uu;
                hist[(size_t)(s * Bx + bb + 0) * Hx + j] = hv4.x;
                hist[(size_t)(s * Bx + bb + 1) * Hx + j] = hv4.y;
                hist[(size_t)(s * Bx + bb + 2) * Hx + j] = hv4.z;
                hist[(size_t)(s * Bx + bb + 3) * Hx + j] = hv4.w;
            }
        }
        // ---- grid barrier ----
        __syncthreads();
        if (tid == 0) {
            __threadfence();
            atomicAdd(bar, 1u);
            unsigned target = nctas * (unsigned)(s + 1);
            while (*((volatile unsigned*)bar) < target) {}
            __threadfence();
        }
        __syncthreads();
    }
}

// ---------------- final FC ---------------------------------------------------
__global__ void fc_kernel(const float* __restrict__ hT, const float* __restrict__ fw,
                          const float* __restrict__ fb, float* __restrict__ out)
{
    __shared__ float hb[Hx];
    int b = blockIdx.x;
    int o = threadIdx.x;          // 128 threads
    for (int j = threadIdx.x; j < Hx; j += OUTx) hb[j] = hT[j * Bx + b];
    __syncthreads();
    float acc = fb[o];
    const float* wr = fw + (size_t)o * Hx;
#pragma unroll 4
    for (int j = 0; j < Hx; j += 4) {
        float4 w = *(const float4*)(wr + j);
        float4 h = *(const float4*)(hb + j);
        acc += w.x * h.x + w.y * h.y + w.z * h.z + w.w * h.w;
    }
    out[b * OUTx + o] = acc;
}

// ---------------- launch ------------------------------------------------------
extern "C" void kernel_launch(void* const* d_in, const int* in_sizes, int n_in,
                              void* d_out, int out_size)
{
    const float* x    = (const float*)d_in[0];
    const float* Wih0 = (const float*)d_in[1];
    const float* Whh0 = (const float*)d_in[2];
    const float* bih0 = (const float*)d_in[3];
    const float* bhh0 = (const float*)d_in[4];
    const float* Wih1 = (const float*)d_in[5];
    const float* Whh1 = (const float*)d_in[6];
    const float* bih1 = (const float*)d_in[7];
    const float* bhh1 = (const float*)d_in[8];
    const float* fcw  = (const float*)d_in[9];
    const float* fcb  = (const float*)d_in[10];
    float* out = (float*)d_out;

    cudaFuncSetAttribute((const void*)lstm_scan_kernel,
                         cudaFuncAttributeMaxDynamicSharedMemorySize, SCAN_SMEM_BYTES);

    void *xg_p, *h1_p, *hT_p;
    cudaGetSymbolAddress(&xg_p, g_xg);
    cudaGetSymbolAddress(&h1_p, g_h1);
    cudaGetSymbolAddress(&hT_p, g_hT);

    init_kernel<<<1, 32>>>();

    dim3 ggrid(Gx / 128, (Sx * Bx) / 128);   // (16, 256)
    // layer 0 input GEMM: xg0 = x @ W_ih0^T + (b_ih0 + b_hh0)
    gemm_xg_kernel<<<ggrid, 256>>>(x, Wih0, bih0, bhh0, (float*)xg_p, Dx, 0);
    // layer 0 scan (writes full h history)
    lstm_scan_kernel<<<128, 256, SCAN_SMEM_BYTES>>>((const float*)xg_p, Whh0,
                                                    (float*)hT_p, (float*)h1_p, 0);
    // layer 1 input GEMM: xg1 = h1 @ W_ih1^T + (b_ih1 + b_hh1)
    gemm_xg_kernel<<<ggrid, 256>>>((const float*)h1_p, Wih1, bih1, bhh1,
                                   (float*)xg_p, Hx, 1);
    // layer 1 scan (only final h needed)
    lstm_scan_kernel<<<128, 256, SCAN_SMEM_BYTES>>>((const float*)xg_p, Whh1,
                                                    (float*)hT_p, nullptr, 1);
    // final FC on last hidden state
    fc_kernel<<<Bx, OUTx>>>((const float*)hT_p, fcw, fcb, out);
}

// round 7
// speedup vs baseline: 1.2891x; 1.0513x over previous
#include <cuda_runtime.h>
#include <cstddef>

#define Bx   64
#define Sx   512
#define Dx   256
#define Hx   512
#define Gx   2048   // 4*H
#define OUTx 128

// ---------------- scratch (static device allocations are the allowed path) ---
__device__ float    g_xg[(size_t)Sx * Bx * Gx];   // 256 MB: gate preactivations [s][b][g]
__device__ float    g_h1[(size_t)Sx * Bx * Hx];   //  64 MB: layer-0 hidden history [s][b][j]
__device__ float    g_hT[Hx * Bx];                // current hidden, TRANSPOSED [j][b]
__device__ unsigned g_bar[2];                     // grid-barrier counters (one per scan launch)

// ---------------- init: zero barrier counters (runs every replay) ------------
__global__ void init_kernel() {
    if (threadIdx.x < 2) g_bar[threadIdx.x] = 0u;
}

// ---------------- big GEMM: C[m][n] = sum_k A[m][k]*W[n][k] + b1[n]+b2[n] -----
// 128x128 tile, 8x8 micro-tile, double-buffered smem, reg-staged LDG.
// M = S*B = 32768 (m -> (s,b)), N = 2048, K = 256 or 512.
// mode 0: A is x[b][s][k]  (row m -> b=m&63, s=m>>6)
// mode 1: A is h1[m][k] contiguous (row stride K)
__global__ void __launch_bounds__(256, 2) gemm_xg_kernel(
    const float* __restrict__ A, const float* __restrict__ W,
    const float* __restrict__ bias1, const float* __restrict__ bias2,
    float* __restrict__ C, int K, int mode)
{
    __shared__ float As[2][8][132];
    __shared__ float Bs[2][8][132];

    const int tid = threadIdx.x;          // 256 threads
    const int m0  = blockIdx.y * 128;
    const int n0  = blockIdx.x * 128;

    // loader mapping: each thread owns one row, one 4-float k-slice
    const int lr = tid >> 1;              // 0..127
    const int lk = (tid & 1) * 4;         // 0 or 4

    const float* aptr;
    if (mode == 0) {
        int m = m0 + lr; int b = m & 63; int s = m >> 6;
        aptr = A + (size_t)b * (Sx * Dx) + (size_t)s * Dx + lk;
    } else {
        aptr = A + (size_t)(m0 + lr) * K + lk;
    }
    const float* wptr = W + (size_t)(n0 + lr) * K + lk;

    const int tx = tid & 15;              // col block (8 cols)
    const int ty = tid >> 4;              // row block (8 rows)

    float acc[8][8];
#pragma unroll
    for (int i = 0; i < 8; ++i)
#pragma unroll
        for (int j = 0; j < 8; ++j) acc[i][j] = 0.f;

    // prologue: tile 0
    {
        float4 a = *(const float4*)aptr;
        float4 w = *(const float4*)wptr;
        As[0][lk+0][lr] = a.x; As[0][lk+1][lr] = a.y;
        As[0][lk+2][lr] = a.z; As[0][lk+3][lr] = a.w;
        Bs[0][lk+0][lr] = w.x; Bs[0][lk+1][lr] = w.y;
        Bs[0][lk+2][lr] = w.z; Bs[0][lk+3][lr] = w.w;
    }
    __syncthreads();

    int buf = 0;
    const int ntiles = K >> 3;
    for (int t = 0; t < ntiles; ++t) {
        float4 an, wn;
        const bool more = (t + 1 < ntiles);
        if (more) {
            an = *(const float4*)(aptr + (t + 1) * 8);
            wn = *(const float4*)(wptr + (t + 1) * 8);
        }
#pragma unroll
        for (int kk = 0; kk < 8; ++kk) {
            float4 a0 = *(const float4*)&As[buf][kk][ty * 8];
            float4 a1 = *(const float4*)&As[buf][kk][ty * 8 + 4];
            float4 b0 = *(const float4*)&Bs[buf][kk][tx * 8];
            float4 b1 = *(const float4*)&Bs[buf][kk][tx * 8 + 4];
            float av[8] = {a0.x, a0.y, a0.z, a0.w, a1.x, a1.y, a1.z, a1.w};
            float bv[8] = {b0.x, b0.y, b0.z, b0.w, b1.x, b1.y, b1.z, b1.w};
#pragma unroll
            for (int i = 0; i < 8; ++i)
#pragma unroll
                for (int j = 0; j < 8; ++j)
                    acc[i][j] = fmaf(av[i], bv[j], acc[i][j]);
        }
        if (more) {
            buf ^= 1;
            As[buf][lk+0][lr] = an.x; As[buf][lk+1][lr] = an.y;
            As[buf][lk+2][lr] = an.z; As[buf][lk+3][lr] = an.w;
            Bs[buf][lk+0][lr] = wn.x; Bs[buf][lk+1][lr] = wn.y;
            Bs[buf][lk+2][lr] = wn.z; Bs[buf][lk+3][lr] = wn.w;
            __syncthreads();
        }
    }

    // epilogue: bias + store
    float4 p1a = *(const float4*)(bias1 + n0 + tx * 8);
    float4 p1b = *(const float4*)(bias1 + n0 + tx * 8 + 4);
    float4 p2a = *(const float4*)(bias2 + n0 + tx * 8);
    float4 p2b = *(const float4*)(bias2 + n0 + tx * 8 + 4);
    float bj[8] = {p1a.x + p2a.x, p1a.y + p2a.y, p1a.z + p2a.z, p1a.w + p2a.w,
                   p1b.x + p2b.x, p1b.y + p2b.y, p1b.z + p2b.z, p1b.w + p2b.w};
#pragma unroll
    for (int i = 0; i < 8; ++i) {
        size_t row = (size_t)(m0 + ty * 8 + i);
        float4 o0, o1;
        o0.x = acc[i][0] + bj[0]; o0.y = acc[i][1] + bj[1];
        o0.z = acc[i][2] + bj[2]; o0.w = acc[i][3] + bj[3];
        o1.x = acc[i][4] + bj[4]; o1.y = acc[i][5] + bj[5];
        o1.z = acc[i][6] + bj[6]; o1.w = acc[i][7] + bj[7];
        *(float4*)(C + row * Gx + n0 + tx * 8)     = o0;
        *(float4*)(C + row * Gx + n0 + tx * 8 + 4) = o1;
    }
}

// ---------------- persistent LSTM scan --------------------------------------
// grid = 128 CTAs (one per 4-hidden-unit block), block = 256 threads (8 warps).
// K=512 split across 4 warp-pair quarters. Each quarter streams its 32 KB slab
// of h in 4 chunks of 32 k, pipelined under the FFMA compute of the previous
// chunk, so the 16 MB/step L2 broadcast hides under the FFMA floor.
#define SCAN_SMEM_FLOATS (Hx*16 + Hx*Bx + 3*16*64 + 16*68 + 4*64)
#define SCAN_SMEM_BYTES  (SCAN_SMEM_FLOATS * 4)

__device__ __forceinline__ float tanhap(float x) {
    float y; asm("tanh.approx.f32 %0, %1;" : "=f"(y) : "f"(x)); return y;
}
__device__ __forceinline__ float sigf(float x) {
    return fmaf(tanhap(x * 0.5f), 0.5f, 0.5f);
}

__global__ void __launch_bounds__(256, 1) lstm_scan_kernel(
    const float* __restrict__ xg,    // [S][B][G] gate preactivations (with biases)
    const float* __restrict__ Whh,   // [G][H]
    float* __restrict__ hT,          // [H][B] current hidden (transposed)
    float* __restrict__ hist,        // [S][B][H] or nullptr
    int barIdx)
{
    extern __shared__ float smf[];
    float* Wt  = smf;                 // [512][16] transposed W tile (resident)
    float* hs  = Wt + Hx * 16;        // [512][64] h transposed
    float* psm = hs + Hx * Bx;        // [3][16][64] K-split partials (quarters 1..3)
    float* gsm = psm + 3 * 16 * 64;   // [16][68]  gates exchange
    float* csm = gsm + 16 * 68;       // [4][64]   cell state (persistent in smem)

    const int tid = threadIdx.x;
    const int cta = blockIdx.x;
    const int u0  = cta * 4;
    unsigned* bar = &g_bar[barIdx];
    const unsigned nctas = gridDim.x;

    // load W tile transposed: Wt[k][r], r = g*4+u -> global row g*H + u0 + u
    {
        int r  = tid & 15;
        int kc = tid >> 4;                       // 0..15 -> k range [kc*32, kc*32+32)
        int g  = r >> 2, u = r & 3;
        const float* wrow = Whh + (size_t)(g * Hx + u0 + u) * Hx;
        for (int k = kc * 32; k < kc * 32 + 32; k += 4) {
            float4 w = *(const float4*)(wrow + k);
            Wt[(k+0)*16 + r] = w.x;
            Wt[(k+1)*16 + r] = w.y;
            Wt[(k+2)*16 + r] = w.z;
            Wt[(k+3)*16 + r] = w.w;
        }
    }
    if (tid < 4 * 64) csm[tid] = 0.f;
    __syncthreads();

    const int quarter = tid >> 6;   // K-split quarter: k in [128*q, 128*q+128)
    const int lt   = tid & 63;
    const int bq   = lt & 15;       // batch quad
    const int rq   = lt >> 4;       // gate index (rows rq*4 .. rq*4+3)
    const int b0   = bq * 4;
    const int k0   = quarter * 128;

    for (int s = 0; s < Sx; ++s) {
        float acc[4][4];
#pragma unroll
        for (int i = 0; i < 4; ++i)
#pragma unroll
            for (int j = 0; j < 4; ++j) acc[i][j] = 0.f;

        // quarter 0 prefetches its xg tail contribution early (hidden latency)
        float4 xv0, xv1, xv2, xv3;
        if (quarter == 0) {
            const float* xb = xg + (size_t)(s * Bx + b0) * Gx + rq * Hx + u0;
            xv0 = __ldcg((const float4*)(xb));
            xv1 = __ldcg((const float4*)(xb + Gx));
            xv2 = __ldcg((const float4*)(xb + 2 * Gx));
            xv3 = __ldcg((const float4*)(xb + 3 * Gx));
        }

        if (s > 0) {
            // stream this quarter's 32 KB h-slab in 4 chunks of 32 k,
            // pipelined: STS(c) -> pair-bar -> LDG(c+1) -> compute(c)
            const float4* srcq = (const float4*)hT + quarter * 2048;
            float4*       dstq = (float4*)hs      + quarter * 2048;
            float4 st[8];
#pragma unroll
            for (int i = 0; i < 8; ++i)
                st[i] = __ldcg(srcq + lt + i * 64);

#pragma unroll
            for (int c = 0; c < 4; ++c) {
#pragma unroll
                for (int i = 0; i < 8; ++i)
                    dstq[c * 512 + lt + i * 64] = st[i];
                asm volatile("bar.sync %0, 64;" :: "r"(quarter + 1) : "memory");
                if (c < 3) {
#pragma unroll
                    for (int i = 0; i < 8; ++i)
                        st[i] = __ldcg(srcq + (c + 1) * 512 + lt + i * 64);
                }
                const float* hp = hs + (size_t)(k0 + 32 * c) * 64 + b0;
                const float* wp = Wt + (size_t)(k0 + 32 * c) * 16 + rq * 4;
#pragma unroll 4
                for (int k = 0; k < 32; ++k) {
                    float4 hv = *(const float4*)(hp + k * 64);
                    float4 wv = *(const float4*)(wp + k * 16);
                    acc[0][0] += hv.x * wv.x; acc[0][1] += hv.x * wv.y;
                    acc[0][2] += hv.x * wv.z; acc[0][3] += hv.x * wv.w;
                    acc[1][0] += hv.y * wv.x; acc[1][1] += hv.y * wv.y;
                    acc[1][2] += hv.y * wv.z; acc[1][3] += hv.y * wv.w;
                    acc[2][0] += hv.z * wv.x; acc[2][1] += hv.z * wv.y;
                    acc[2][2] += hv.z * wv.z; acc[2][3] += hv.z * wv.w;
                    acc[3][0] += hv.w * wv.x; acc[3][1] += hv.w * wv.y;
                    acc[3][2] += hv.w * wv.z; acc[3][3] += hv.w * wv.w;
                }
            }
        }
        __syncthreads();
        if (quarter != 0) {
            float* pq = psm + (quarter - 1) * (16 * 64);
#pragma unroll
            for (int j = 0; j < 4; ++j) {
                float4 v = make_float4(acc[0][j], acc[1][j], acc[2][j], acc[3][j]);
                *(float4*)&pq[(rq * 4 + j) * 64 + b0] = v;
            }
        }
        __syncthreads();
        if (quarter == 0) {
            acc[0][0] += xv0.x; acc[0][1] += xv0.y; acc[0][2] += xv0.z; acc[0][3] += xv0.w;
            acc[1][0] += xv1.x; acc[1][1] += xv1.y; acc[1][2] += xv1.z; acc[1][3] += xv1.w;
            acc[2][0] += xv2.x; acc[2][1] += xv2.y; acc[2][2] += xv2.z; acc[2][3] += xv2.w;
            acc[3][0] += xv3.x; acc[3][1] += xv3.y; acc[3][2] += xv3.z; acc[3][3] += xv3.w;
#pragma unroll
            for (int j = 0; j < 4; ++j) {
                float4 p0 = *(const float4*)&psm[0 * 1024 + (rq * 4 + j) * 64 + b0];
                float4 p1 = *(const float4*)&psm[1 * 1024 + (rq * 4 + j) * 64 + b0];
                float4 p2 = *(const float4*)&psm[2 * 1024 + (rq * 4 + j) * 64 + b0];
                float4 v = make_float4(acc[0][j] + p0.x + p1.x + p2.x,
                                       acc[1][j] + p0.y + p1.y + p2.y,
                                       acc[2][j] + p0.z + p1.z + p2.z,
                                       acc[3][j] + p0.w + p1.w + p2.w);
                *(float4*)&gsm[(rq * 4 + j) * 68 + b0] = v;
            }
        }
        __syncthreads();
        if (tid < 64) {
            int uu = tid >> 4;
            int bb = (tid & 15) * 4;
            float4 iv = *(const float4*)&gsm[( 0 + uu) * 68 + bb];
            float4 fv = *(const float4*)&gsm[( 4 + uu) * 68 + bb];
            float4 gv = *(const float4*)&gsm[( 8 + uu) * 68 + bb];
            float4 ov = *(const float4*)&gsm[(12 + uu) * 68 + bb];
            float4 cv = *(float4*)&csm[uu * 64 + bb];
            float4 hv4;
#define LSTM_ELEM(X) { \
            float ci = sigf(iv.X); float cf = sigf(fv.X); \
            float cg = tanhap(gv.X); float co = sigf(ov.X); \
            cv.X = cf * cv.X + ci * cg; \
            hv4.X = co * tanhap(cv.X); }
            LSTM_ELEM(x) LSTM_ELEM(y) LSTM_ELEM(z) LSTM_ELEM(w)
#undef LSTM_ELEM
            *(float4*)&csm[uu * 64 + bb] = cv;
            *(float4*)(hT + (size_t)(u0 + uu) * Bx + bb) = hv4;
            if (hist) {
                int j = u0 + uu;
                hist[(size_t)(s * Bx + bb + 0) * Hx + j] = hv4.x;
                hist[(size_t)(s * Bx + bb + 1) * Hx + j] = hv4.y;
                hist[(size_t)(s * Bx + bb + 2) * Hx + j] = hv4.z;
                hist[(size_t)(s * Bx + bb + 3) * Hx + j] = hv4.w;
            }
        }
        // ---- grid barrier ----
        __syncthreads();
        if (tid == 0) {
            __threadfence();
            atomicAdd(bar, 1u);
            unsigned target = nctas * (unsigned)(s + 1);
            while (*((volatile unsigned*)bar) < target) {}
            __threadfence();
        }
        __syncthreads();
    }
}

// ---------------- final FC ---------------------------------------------------
__global__ void fc_kernel(const float* __restrict__ hT, const float* __restrict__ fw,
                          const float* __restrict__ fb, float* __restrict__ out)
{
    __shared__ float hb[Hx];
    int b = blockIdx.x;
    int o = threadIdx.x;          // 128 threads
    for (int j = threadIdx.x; j < Hx; j += OUTx) hb[j] = hT[j * Bx + b];
    __syncthreads();
    float acc = fb[o];
    const float* wr = fw + (size_t)o * Hx;
#pragma unroll 4
    for (int j = 0; j < Hx; j += 4) {
        float4 w = *(const float4*)(wr + j);
        float4 h = *(const float4*)(hb + j);
        acc += w.x * h.x + w.y * h.y + w.z * h.z + w.w * h.w;
    }
    out[b * OUTx + o] = acc;
}

// ---------------- launch ------------------------------------------------------
extern "C" void kernel_launch(void* const* d_in, const int* in_sizes, int n_in,
                              void* d_out, int out_size)
{
    const float* x    = (const float*)d_in[0];
    const float* Wih0 = (const float*)d_in[1];
    const float* Whh0 = (const float*)d_in[2];
    const float* bih0 = (const float*)d_in[3];
    const float* bhh0 = (const float*)d_in[4];
    const float* Wih1 = (const float*)d_in[5];
    const float* Whh1 = (const float*)d_in[6];
    const float* bih1 = (const float*)d_in[7];
    const float* bhh1 = (const float*)d_in[8];
    const float* fcw  = (const float*)d_in[9];
    const float* fcb  = (const float*)d_in[10];
    float* out = (float*)d_out;

    cudaFuncSetAttribute((const void*)lstm_scan_kernel,
                         cudaFuncAttributeMaxDynamicSharedMemorySize, SCAN_SMEM_BYTES);

    void *xg_p, *h1_p, *hT_p;
    cudaGetSymbolAddress(&xg_p, g_xg);
    cudaGetSymbolAddress(&h1_p, g_h1);
    cudaGetSymbolAddress(&hT_p, g_hT);

    init_kernel<<<1, 32>>>();

    dim3 ggrid(Gx / 128, (Sx * Bx) / 128);   // (16, 256)
    // layer 0 input GEMM: xg0 = x @ W_ih0^T + (b_ih0 + b_hh0)
    gemm_xg_kernel<<<ggrid, 256>>>(x, Wih0, bih0, bhh0, (float*)xg_p, Dx, 0);
    // layer 0 scan (writes full h history)
    lstm_scan_kernel<<<128, 256, SCAN_SMEM_BYTES>>>((const float*)xg_p, Whh0,
                                                    (float*)hT_p, (float*)h1_p, 0);
    // layer 1 input GEMM: xg1 = h1 @ W_ih1^T + (b_ih1 + b_hh1)
    gemm_xg_kernel<<<ggrid, 256>>>((const float*)h1_p, Wih1, bih1, bhh1,
                                   (float*)xg_p, Hx, 1);
    // layer 1 scan (only final h needed)
    lstm_scan_kernel<<<128, 256, SCAN_SMEM_BYTES>>>((const float*)xg_p, Whh1,
                                                    (float*)hT_p, nullptr, 1);
    // final FC on last hidden state
    fc_kernel<<<Bx, OUTx>>>((const float*)hT_p, fcw, fcb, out);
}

// round 9
// speedup vs baseline: 1.3891x; 1.0776x over previous
#include <cuda_runtime.h>
#include <cuda_bf16.h>
#include <mma.h>
#include <cstdint>
#include <cstddef>

using namespace nvcuda;

#define Bx   64
#define Sx   512
#define Dx   256
#define Hx   512
#define Gx   2048   // 4*H
#define OUTx 128

// ---------------- scratch (static device allocations are the allowed path) ---
__device__ float          g_xg[(size_t)Sx * Bx * Gx];     // 256 MB gate preacts [s][b][g] (NO bias)
__device__ float          g_h1[(size_t)Sx * Bx * Hx];     //  64 MB layer-0 hidden history
__device__ float          g_hT[Hx * Bx];                  // current hidden, transposed [j][b]
__device__ unsigned       g_bar[2];                       // grid-barrier counters
__device__ __nv_bfloat16  g_A2[(size_t)Sx * Bx * 3 * Hx]; // 96 MB split-A [m][3K]
__device__ __nv_bfloat16  g_W2[(size_t)Gx * 3 * Hx];      //  6 MB split-W [n][3K]

__global__ void init_kernel() {
    if (threadIdx.x < 2) g_bar[threadIdx.x] = 0u;
}

// ---------------- fp32 -> (hi,lo) bf16 split conversions ---------------------
// A2 row = [hi, hi, lo], W2 row = [hi, lo, hi]  =>  sum over 3K = hh + hl + lh
__global__ void conv_w_kernel(const float* __restrict__ W, __nv_bfloat16* __restrict__ W2, int K)
{
    int n = blockIdx.x;
    const float* src = W + (size_t)n * K;
    __nv_bfloat16* dst = W2 + (size_t)n * 3 * K;
    for (int k = threadIdx.x; k < K; k += blockDim.x) {
        float v = src[k];
        __nv_bfloat16 hi = __float2bfloat16(v);
        __nv_bfloat16 lo = __float2bfloat16(v - __bfloat162float(hi));
        dst[k] = hi; dst[K + k] = lo; dst[2 * K + k] = hi;
    }
}

__global__ void conv_a_kernel(const float* __restrict__ A, __nv_bfloat16* __restrict__ A2,
                              int K, int mode)
{
    int m = blockIdx.x;   // m = s*64 + b
    const float* src = (mode == 0)
        ? (A + (size_t)(m & 63) * (Sx * Dx) + (size_t)(m >> 6) * Dx)
        : (A + (size_t)m * K);
    __nv_bfloat16* dst = A2 + (size_t)m * 3 * K;
    for (int k = threadIdx.x; k < K; k += blockDim.x) {
        float v = src[k];
        __nv_bfloat16 hi = __float2bfloat16(v);
        __nv_bfloat16 lo = __float2bfloat16(v - __bfloat162float(hi));
        dst[k] = hi; dst[K + k] = hi; dst[2 * K + k] = lo;
    }
}

// ---------------- HMMA (wmma) GEMM: C[m][n] = sum_3K A2[m][k]*W2[n][k] -------
// grid = (Gx/128, M/128); block = 256 (8 warps). 128x128 CTA tile;
// warp tile 64x32 = 4x2 m16n16k16 frags. K-tile 32, double-buffered smem.
#define LDP 40   // padded row length (bf16 elems) for smem tiles

__global__ void __launch_bounds__(256, 1) wmma_gemm_kernel(
    const __nv_bfloat16* __restrict__ A2, const __nv_bfloat16* __restrict__ W2,
    float* __restrict__ C, int Ktot)
{
    __shared__ __align__(16) __nv_bfloat16 As[2][128 * LDP];
    __shared__ __align__(16) __nv_bfloat16 Bs[2][128 * LDP];

    const int tid = threadIdx.x;
    const int wid = tid >> 5;
    const int m0 = blockIdx.y * 128;
    const int n0 = blockIdx.x * 128;
    const int wm = (wid >> 2) * 64;        // warp row offset within tile
    const int wn = (wid & 3) * 32;         // warp col offset within tile

    wmma::fragment<wmma::accumulator, 16, 16, 16, float> acc[4][2];
#pragma unroll
    for (int i = 0; i < 4; ++i)
#pragma unroll
        for (int j = 0; j < 2; ++j) wmma::fill_fragment(acc[i][j], 0.f);

    // loader mapping: 512 16-byte chunks per (A or B) tile; 2 chunks/thread.
    // chunk c -> row = c>>2 (0..127), q = c&3 (16B slice within 64B row)
    const int ca = tid, cb = tid + 256;
    const int ra = ca >> 2, qa = ca & 3;
    const int rb = cb >> 2, qb = cb & 3;
    const char* Ag = (const char*)A2;
    const char* Bg = (const char*)W2;
    const size_t aoff0 = ((size_t)(m0 + ra) * Ktot + qa * 8) * 2;
    const size_t aoff1 = ((size_t)(m0 + rb) * Ktot + qb * 8) * 2;
    const size_t boff0 = ((size_t)(n0 + ra) * Ktot + qa * 8) * 2;
    const size_t boff1 = ((size_t)(n0 + rb) * Ktot + qb * 8) * 2;
    const int s0 = ra * (LDP * 2) + qa * 16;   // smem byte offsets
    const int s1 = rb * (LDP * 2) + qb * 16;

    // prologue: k-tile 0 -> buf 0
    {
        uint4 a0 = *(const uint4*)(Ag + aoff0);
        uint4 a1 = *(const uint4*)(Ag + aoff1);
        uint4 b0 = *(const uint4*)(Bg + boff0);
        uint4 b1 = *(const uint4*)(Bg + boff1);
        *(uint4*)((char*)As[0] + s0) = a0;
        *(uint4*)((char*)As[0] + s1) = a1;
        *(uint4*)((char*)Bs[0] + s0) = b0;
        *(uint4*)((char*)Bs[0] + s1) = b1;
    }
    __syncthreads();

    const int T = Ktot >> 5;   // 32-k tiles
    for (int t = 0; t < T; ++t) {
        const int buf = t & 1;
        const bool more = (t + 1 < T);
        uint4 na0, na1, nb0, nb1;
        if (more) {
            size_t ko = (size_t)(t + 1) * 64;   // 32 bf16 = 64 bytes
            na0 = *(const uint4*)(Ag + aoff0 + ko);
            na1 = *(const uint4*)(Ag + aoff1 + ko);
            nb0 = *(const uint4*)(Bg + boff0 + ko);
            nb1 = *(const uint4*)(Bg + boff1 + ko);
        }
#pragma unroll
        for (int ks = 0; ks < 2; ++ks) {
            wmma::fragment<wmma::matrix_a, 16, 16, 16, __nv_bfloat16, wmma::row_major> af[4];
            wmma::fragment<wmma::matrix_b, 16, 16, 16, __nv_bfloat16, wmma::col_major> bf[2];
#pragma unroll
            for (int i = 0; i < 4; ++i)
                wmma::load_matrix_sync(af[i], &As[buf][(wm + i * 16) * LDP + ks * 16], LDP);
#pragma unroll
            for (int j = 0; j < 2; ++j)
                wmma::load_matrix_sync(bf[j], &Bs[buf][(wn + j * 16) * LDP + ks * 16], LDP);
#pragma unroll
            for (int i = 0; i < 4; ++i)
#pragma unroll
                for (int j = 0; j < 2; ++j)
                    wmma::mma_sync(acc[i][j], af[i], bf[j], acc[i][j]);
        }
        if (more) {
            const int nb = buf ^ 1;
            *(uint4*)((char*)As[nb] + s0) = na0;
            *(uint4*)((char*)As[nb] + s1) = na1;
            *(uint4*)((char*)Bs[nb] + s0) = nb0;
            *(uint4*)((char*)Bs[nb] + s1) = nb1;
            __syncthreads();
        }
    }

    // epilogue: store fp32 tiles (bias is folded into the scan)
#pragma unroll
    for (int i = 0; i < 4; ++i)
#pragma unroll
        for (int j = 0; j < 2; ++j)
            wmma::store_matrix_sync(
                C + (size_t)(m0 + wm + i * 16) * Gx + n0 + wn + j * 16,
                acc[i][j], Gx, wmma::mem_row_major);
}

// ---------------- persistent LSTM scan (R7 structure + bias fold) ------------
#define SCAN_SMEM_FLOATS (Hx*16 + Hx*Bx + 3*16*64 + 16*68 + 4*64)
#define SCAN_SMEM_BYTES  (SCAN_SMEM_FLOATS * 4)

__device__ __forceinline__ float tanhap(float x) {
    float y; asm("tanh.approx.f32 %0, %1;" : "=f"(y) : "f"(x)); return y;
}
__device__ __forceinline__ float sigf(float x) {
    return fmaf(tanhap(x * 0.5f), 0.5f, 0.5f);
}

__global__ void __launch_bounds__(256, 1) lstm_scan_kernel(
    const float* __restrict__ xg, const float* __restrict__ Whh,
    const float* __restrict__ bias1, const float* __restrict__ bias2,
    float* __restrict__ hT, float* __restrict__ hist, int barIdx)
{
    extern __shared__ float smf[];
    float* Wt  = smf;
    float* hs  = Wt + Hx * 16;
    float* psm = hs + Hx * Bx;
    float* gsm = psm + 3 * 16 * 64;
    float* csm = gsm + 16 * 68;

    const int tid = threadIdx.x;
    const int cta = blockIdx.x;
    const int u0  = cta * 4;
    unsigned* bar = &g_bar[barIdx];
    const unsigned nctas = gridDim.x;

    {
        int r  = tid & 15;
        int kc = tid >> 4;
        int g  = r >> 2, u = r & 3;
        const float* wrow = Whh + (size_t)(g * Hx + u0 + u) * Hx;
        for (int k = kc * 32; k < kc * 32 + 32; k += 4) {
            float4 w = *(const float4*)(wrow + k);
            Wt[(k+0)*16 + r] = w.x;
            Wt[(k+1)*16 + r] = w.y;
            Wt[(k+2)*16 + r] = w.z;
            Wt[(k+3)*16 + r] = w.w;
        }
    }
    if (tid < 4 * 64) csm[tid] = 0.f;
    __syncthreads();

    const int quarter = tid >> 6;
    const int lt   = tid & 63;
    const int bq   = lt & 15;
    const int rq   = lt >> 4;
    const int b0   = bq * 4;
    const int k0   = quarter * 128;

    // combined bias for this thread's 4 gate columns (quarter 0 only)
    float4 bb4 = make_float4(0.f, 0.f, 0.f, 0.f);
    if (quarter == 0) {
        const float* p1 = bias1 + rq * Hx + u0;
        const float* p2 = bias2 + rq * Hx + u0;
        bb4.x = p1[0] + p2[0]; bb4.y = p1[1] + p2[1];
        bb4.z = p1[2] + p2[2]; bb4.w = p1[3] + p2[3];
    }

    for (int s = 0; s < Sx; ++s) {
        float acc[4][4];
#pragma unroll
        for (int i = 0; i < 4; ++i)
#pragma unroll
            for (int j = 0; j < 4; ++j) acc[i][j] = 0.f;

        float4 xv0, xv1, xv2, xv3;
        if (quarter == 0) {
            const float* xb = xg + (size_t)(s * Bx + b0) * Gx + rq * Hx + u0;
            xv0 = __ldcg((const float4*)(xb));
            xv1 = __ldcg((const float4*)(xb + Gx));
            xv2 = __ldcg((const float4*)(xb + 2 * Gx));
            xv3 = __ldcg((const float4*)(xb + 3 * Gx));
            xv0.x += bb4.x; xv0.y += bb4.y; xv0.z += bb4.z; xv0.w += bb4.w;
            xv1.x += bb4.x; xv1.y += bb4.y; xv1.z += bb4.z; xv1.w += bb4.w;
            xv2.x += bb4.x; xv2.y += bb4.y; xv2.z += bb4.z; xv2.w += bb4.w;
            xv3.x += bb4.x; xv3.y += bb4.y; xv3.z += bb4.z; xv3.w += bb4.w;
        }

        if (s > 0) {
            const float4* srcq = (const float4*)hT + quarter * 2048;
            float4*       dstq = (float4*)hs      + quarter * 2048;
            float4 st[8];
#pragma unroll
            for (int i = 0; i < 8; ++i)
                st[i] = __ldcg(srcq + lt + i * 64);

#pragma unroll
            for (int c = 0; c < 4; ++c) {
#pragma unroll
                for (int i = 0; i < 8; ++i)
                    dstq[c * 512 + lt + i * 64] = st[i];
                asm volatile("bar.sync %0, 64;" :: "r"(quarter + 1) : "memory");
                if (c < 3) {
#pragma unroll
                    for (int i = 0; i < 8; ++i)
                        st[i] = __ldcg(srcq + (c + 1) * 512 + lt + i * 64);
                }
                const float* hp = hs + (size_t)(k0 + 32 * c) * 64 + b0;
                const float* wp = Wt + (size_t)(k0 + 32 * c) * 16 + rq * 4;
#pragma unroll 4
                for (int k = 0; k < 32; ++k) {
                    float4 hv = *(const float4*)(hp + k * 64);
                    float4 wv = *(const float4*)(wp + k * 16);
                    acc[0][0] += hv.x * wv.x; acc[0][1] += hv.x * wv.y;
                    acc[0][2] += hv.x * wv.z; acc[0][3] += hv.x * wv.w;
                    acc[1][0] += hv.y * wv.x; acc[1][1] += hv.y * wv.y;
                    acc[1][2] += hv.y * wv.z; acc[1][3] += hv.y * wv.w;
                    acc[2][0] += hv.z * wv.x; acc[2][1] += hv.z * wv.y;
                    acc[2][2] += hv.z * wv.z; acc[2][3] += hv.z * wv.w;
                    acc[3][0] += hv.w * wv.x; acc[3][1] += hv.w * wv.y;
                    acc[3][2] += hv.w * wv.z; acc[3][3] += hv.w * wv.w;
                }
            }
        }
        __syncthreads();
        if (quarter != 0) {
            float* pq = psm + (quarter - 1) * (16 * 64);
#pragma unroll
            for (int j = 0; j < 4; ++j) {
                float4 v = make_float4(acc[0][j], acc[1][j], acc[2][j], acc[3][j]);
                *(float4*)&pq[(rq * 4 + j) * 64 + b0] = v;
            }
        }
        __syncthreads();
        if (quarter == 0) {
            acc[0][0] += xv0.x; acc[0][1] += xv0.y; acc[0][2] += xv0.z; acc[0][3] += xv0.w;
            acc[1][0] += xv1.x; acc[1][1] += xv1.y; acc[1][2] += xv1.z; acc[1][3] += xv1.w;
            acc[2][0] += xv2.x; acc[2][1] += xv2.y; acc[2][2] += xv2.z; acc[2][3] += xv2.w;
            acc[3][0] += xv3.x; acc[3][1] += xv3.y; acc[3][2] += xv3.z; acc[3][3] += xv3.w;
#pragma unroll
            for (int j = 0; j < 4; ++j) {
                float4 p0 = *(const float4*)&psm[0 * 1024 + (rq * 4 + j) * 64 + b0];
                float4 p1 = *(const float4*)&psm[1 * 1024 + (rq * 4 + j) * 64 + b0];
                float4 p2 = *(const float4*)&psm[2 * 1024 + (rq * 4 + j) * 64 + b0];
                float4 v = make_float4(acc[0][j] + p0.x + p1.x + p2.x,
                                       acc[1][j] + p0.y + p1.y + p2.y,
                                       acc[2][j] + p0.z + p1.z + p2.z,
                                       acc[3][j] + p0.w + p1.w + p2.w);
                *(float4*)&gsm[(rq * 4 + j) * 68 + b0] = v;
            }
        }
        __syncthreads();
        if (tid < 64) {
            int uu = tid >> 4;
            int bb = (tid & 15) * 4;
            float4 iv = *(const float4*)&gsm[( 0 + uu) * 68 + bb];
            float4 fv = *(const float4*)&gsm[( 4 + uu) * 68 + bb];
            float4 gv = *(const float4*)&gsm[( 8 + uu) * 68 + bb];
            float4 ov = *(const float4*)&gsm[(12 + uu) * 68 + bb];
            float4 cv = *(float4*)&csm[uu * 64 + bb];
            float4 hv4;
#define LSTM_ELEM(X) { \
            float ci = sigf(iv.X); float cf = sigf(fv.X); \
            float cg = tanhap(gv.X); float co = sigf(ov.X); \
            cv.X = cf * cv.X + ci * cg; \
            hv4.X = co * tanhap(cv.X); }
            LSTM_ELEM(x) LSTM_ELEM(y) LSTM_ELEM(z) LSTM_ELEM(w)
#undef LSTM_ELEM
            *(float4*)&csm[uu * 64 + bb] = cv;
            *(float4*)(hT + (size_t)(u0 + uu) * Bx + bb) = hv4;
            if (hist) {
                int j = u0 + uu;
                hist[(size_t)(s * Bx + bb + 0) * Hx + j] = hv4.x;
                hist[(size_t)(s * Bx + bb + 1) * Hx + j] = hv4.y;
                hist[(size_t)(s * Bx + bb + 2) * Hx + j] = hv4.z;
                hist[(size_t)(s * Bx + bb + 3) * Hx + j] = hv4.w;
            }
        }
        __syncthreads();
        if (tid == 0) {
            __threadfence();
            atomicAdd(bar, 1u);
            unsigned target = nctas * (unsigned)(s + 1);
            while (*((volatile unsigned*)bar) < target) {}
            __threadfence();
        }
        __syncthreads();
    }
}

// ---------------- final FC ---------------------------------------------------
__global__ void fc_kernel(const float* __restrict__ hT, const float* __restrict__ fw,
                          const float* __restrict__ fb, float* __restrict__ out)
{
    __shared__ float hb[Hx];
    int b = blockIdx.x;
    int o = threadIdx.x;
    for (int j = threadIdx.x; j < Hx; j += OUTx) hb[j] = hT[j * Bx + b];
    __syncthreads();
    float acc = fb[o];
    const float* wr = fw + (size_t)o * Hx;
#pragma unroll 4
    for (int j = 0; j < Hx; j += 4) {
        float4 w = *(const float4*)(wr + j);
        float4 h = *(const float4*)(hb + j);
        acc += w.x * h.x + w.y * h.y + w.z * h.z + w.w * h.w;
    }
    out[b * OUTx + o] = acc;
}

// ---------------- launch ------------------------------------------------------
extern "C" void kernel_launch(void* const* d_in, const int* in_sizes, int n_in,
                              void* d_out, int out_size)
{
    const float* x    = (const float*)d_in[0];
    const float* Wih0 = (const float*)d_in[1];
    const float* Whh0 = (const float*)d_in[2];
    const float* bih0 = (const float*)d_in[3];
    const float* bhh0 = (const float*)d_in[4];
    const float* Wih1 = (const float*)d_in[5];
    const float* Whh1 = (const float*)d_in[6];
    const float* bih1 = (const float*)d_in[7];
    const float* bhh1 = (const float*)d_in[8];
    const float* fcw  = (const float*)d_in[9];
    const float* fcb  = (const float*)d_in[10];
    float* out = (float*)d_out;

    cudaFuncSetAttribute((const void*)lstm_scan_kernel,
                         cudaFuncAttributeMaxDynamicSharedMemorySize, SCAN_SMEM_BYTES);

    void *xg_p, *h1_p, *hT_p, *a2_p, *w2_p;
    cudaGetSymbolAddress(&xg_p, g_xg);
    cudaGetSymbolAddress(&h1_p, g_h1);
    cudaGetSymbolAddress(&hT_p, g_hT);
    cudaGetSymbolAddress(&a2_p, g_A2);
    cudaGetSymbolAddress(&w2_p, g_W2);

    init_kernel<<<1, 32>>>();

    dim3 mgrid(Gx / 128, (Sx * Bx) / 128);   // (16, 256)

    // ---- layer 0: xg0 = x @ Wih0^T (split-bf16 HMMA), bias folded into scan --
    conv_w_kernel<<<Gx, 128>>>(Wih0, (__nv_bfloat16*)w2_p, Dx);
    conv_a_kernel<<<Sx * Bx, 128>>>(x, (__nv_bfloat16*)a2_p, Dx, 0);
    wmma_gemm_kernel<<<mgrid, 256>>>(
        (const __nv_bfloat16*)a2_p, (const __nv_bfloat16*)w2_p,
        (float*)xg_p, 3 * Dx);
    lstm_scan_kernel<<<128, 256, SCAN_SMEM_BYTES>>>((const float*)xg_p, Whh0,
                                                    bih0, bhh0,
                                                    (float*)hT_p, (float*)h1_p, 0);

    // ---- layer 1: xg1 = h1 @ Wih1^T ----
    conv_w_kernel<<<Gx, 128>>>(Wih1, (__nv_bfloat16*)w2_p, Hx);
    conv_a_kernel<<<Sx * Bx, 128>>>((const float*)h1_p, (__nv_bfloat16*)a2_p, Hx, 1);
    wmma_gemm_kernel<<<mgrid, 256>>>(
        (const __nv_bfloat16*)a2_p, (const __nv_bfloat16*)w2_p,
        (float*)xg_p, 3 * Hx);
    lstm_scan_kernel<<<128, 256, SCAN_SMEM_BYTES>>>((const float*)xg_p, Whh1,
                                                    bih1, bhh1,
                                                    (float*)hT_p, nullptr, 1);

    fc_kernel<<<Bx, OUTx>>>((const float*)hT_p, fcw, fcb, out);
}

// round 10
// speedup vs baseline: 1.6969x; 1.2216x over previous
#include <cuda_runtime.h>
#include <cuda_bf16.h>
#include <mma.h>
#include <cstdint>
#include <cstddef>

using namespace nvcuda;

#define Bx   64
#define Sx   512
#define Dx   256
#define Hx   512
#define Gx   2048   // 4*H
#define OUTx 128

// ---------------- scratch (static device allocations are the allowed path) ---
__device__ float          g_xg[(size_t)Sx * Bx * Gx];     // 256 MB gate preacts (no bias)
__device__ float          g_h1[(size_t)Sx * Bx * Hx];     //  64 MB layer-0 hidden history
__device__ float          g_hC[Bx * Hx];                  // current hidden fp32 [b][j]
__device__ __nv_bfloat16  g_hHi[Bx * Hx];                 // current hidden bf16 hi [b][j]
__device__ __nv_bfloat16  g_hLo[Bx * Hx];                 // current hidden bf16 lo [b][j]
__device__ unsigned       g_bar[2];                       // grid-barrier counters
__device__ __nv_bfloat16  g_A2[(size_t)Sx * Bx * 3 * Hx]; // 96 MB split-A [m][3K]
__device__ __nv_bfloat16  g_W2[(size_t)Gx * 3 * Hx];      //  6 MB split-W [n][3K]

__global__ void init_kernel() {
    if (threadIdx.x < 2) g_bar[threadIdx.x] = 0u;
}

// ---------------- fp32 -> (hi,lo) bf16 split conversions ---------------------
__global__ void conv_w_kernel(const float* __restrict__ W, __nv_bfloat16* __restrict__ W2, int K)
{
    int n = blockIdx.x;
    const float* src = W + (size_t)n * K;
    __nv_bfloat16* dst = W2 + (size_t)n * 3 * K;
    for (int k = threadIdx.x; k < K; k += blockDim.x) {
        float v = src[k];
        __nv_bfloat16 hi = __float2bfloat16(v);
        __nv_bfloat16 lo = __float2bfloat16(v - __bfloat162float(hi));
        dst[k] = hi; dst[K + k] = lo; dst[2 * K + k] = hi;
    }
}

__global__ void conv_a_kernel(const float* __restrict__ A, __nv_bfloat16* __restrict__ A2,
                              int K, int mode)
{
    int m = blockIdx.x;   // m = s*64 + b
    const float* src = (mode == 0)
        ? (A + (size_t)(m & 63) * (Sx * Dx) + (size_t)(m >> 6) * Dx)
        : (A + (size_t)m * K);
    __nv_bfloat16* dst = A2 + (size_t)m * 3 * K;
    for (int k = threadIdx.x; k < K; k += blockDim.x) {
        float v = src[k];
        __nv_bfloat16 hi = __float2bfloat16(v);
        __nv_bfloat16 lo = __float2bfloat16(v - __bfloat162float(hi));
        dst[k] = hi; dst[K + k] = hi; dst[2 * K + k] = lo;
    }
}

// ---------------- HMMA (wmma) GEMM for input projections (unchanged R9) ------
#define LDP 40

__global__ void __launch_bounds__(256, 1) wmma_gemm_kernel(
    const __nv_bfloat16* __restrict__ A2, const __nv_bfloat16* __restrict__ W2,
    float* __restrict__ C, int Ktot)
{
    __shared__ __align__(16) __nv_bfloat16 As[2][128 * LDP];
    __shared__ __align__(16) __nv_bfloat16 Bs[2][128 * LDP];

    const int tid = threadIdx.x;
    const int wid = tid >> 5;
    const int m0 = blockIdx.y * 128;
    const int n0 = blockIdx.x * 128;
    const int wm = (wid >> 2) * 64;
    const int wn = (wid & 3) * 32;

    wmma::fragment<wmma::accumulator, 16, 16, 16, float> acc[4][2];
#pragma unroll
    for (int i = 0; i < 4; ++i)
#pragma unroll
        for (int j = 0; j < 2; ++j) wmma::fill_fragment(acc[i][j], 0.f);

    const int ca = tid, cb = tid + 256;
    const int ra = ca >> 2, qa = ca & 3;
    const int rb = cb >> 2, qb = cb & 3;
    const char* Ag = (const char*)A2;
    const char* Bg = (const char*)W2;
    const size_t aoff0 = ((size_t)(m0 + ra) * Ktot + qa * 8) * 2;
    const size_t aoff1 = ((size_t)(m0 + rb) * Ktot + qb * 8) * 2;
    const size_t boff0 = ((size_t)(n0 + ra) * Ktot + qa * 8) * 2;
    const size_t boff1 = ((size_t)(n0 + rb) * Ktot + qb * 8) * 2;
    const int s0 = ra * (LDP * 2) + qa * 16;
    const int s1 = rb * (LDP * 2) + qb * 16;

    {
        uint4 a0 = *(const uint4*)(Ag + aoff0);
        uint4 a1 = *(const uint4*)(Ag + aoff1);
        uint4 b0 = *(const uint4*)(Bg + boff0);
        uint4 b1 = *(const uint4*)(Bg + boff1);
        *(uint4*)((char*)As[0] + s0) = a0;
        *(uint4*)((char*)As[0] + s1) = a1;
        *(uint4*)((char*)Bs[0] + s0) = b0;
        *(uint4*)((char*)Bs[0] + s1) = b1;
    }
    __syncthreads();

    const int T = Ktot >> 5;
    for (int t = 0; t < T; ++t) {
        const int buf = t & 1;
        const bool more = (t + 1 < T);
        uint4 na0, na1, nb0, nb1;
        if (more) {
            size_t ko = (size_t)(t + 1) * 64;
            na0 = *(const uint4*)(Ag + aoff0 + ko);
            na1 = *(const uint4*)(Ag + aoff1 + ko);
            nb0 = *(const uint4*)(Bg + boff0 + ko);
            nb1 = *(const uint4*)(Bg + boff1 + ko);
        }
#pragma unroll
        for (int ks = 0; ks < 2; ++ks) {
            wmma::fragment<wmma::matrix_a, 16, 16, 16, __nv_bfloat16, wmma::row_major> af[4];
            wmma::fragment<wmma::matrix_b, 16, 16, 16, __nv_bfloat16, wmma::col_major> bf[2];
#pragma unroll
            for (int i = 0; i < 4; ++i)
                wmma::load_matrix_sync(af[i], &As[buf][(wm + i * 16) * LDP + ks * 16], LDP);
#pragma unroll
            for (int j = 0; j < 2; ++j)
                wmma::load_matrix_sync(bf[j], &Bs[buf][(wn + j * 16) * LDP + ks * 16], LDP);
#pragma unroll
            for (int i = 0; i < 4; ++i)
#pragma unroll
                for (int j = 0; j < 2; ++j)
                    wmma::mma_sync(acc[i][j], af[i], bf[j], acc[i][j]);
        }
        if (more) {
            const int nb = buf ^ 1;
            *(uint4*)((char*)As[nb] + s0) = na0;
            *(uint4*)((char*)As[nb] + s1) = na1;
            *(uint4*)((char*)Bs[nb] + s0) = nb0;
            *(uint4*)((char*)Bs[nb] + s1) = nb1;
            __syncthreads();
        }
    }

#pragma unroll
    for (int i = 0; i < 4; ++i)
#pragma unroll
        for (int j = 0; j < 2; ++j)
            wmma::store_matrix_sync(
                C + (size_t)(m0 + wm + i * 16) * Gx + n0 + wn + j * 16,
                acc[i][j], Gx, wmma::mem_row_major);
}

// ---------------- persistent LSTM scan on tensor cores -----------------------
// grid = 128 CTAs (16 gate rows each), block = 256 (8 warps, k-split 64 each).
// Per step: C[64b x 16r] = h_hi*W_hi + h_hi*W_lo + h_lo*W_hi (split-bf16, fp32 acc).
// W B-fragments live in registers for all 512 steps. h staged in smem per step.
#define PW      520                    // padded A/W row length (bf16 elems)
#define AHI_OFF 0
#define ALO_OFF 66560
#define WRD_OFF 133120                 // W split during prologue; partial-C in loop
#define GSM_OFF 166400
#define CSM_OFF 170752
#define BSM_OFF 171776
#define SCAN2_SMEM 171840

__device__ __forceinline__ float tanhap(float x) {
    float y; asm("tanh.approx.f32 %0, %1;" : "=f"(y) : "f"(x)); return y;
}
__device__ __forceinline__ float sigf(float x) {
    return fmaf(tanhap(x * 0.5f), 0.5f, 0.5f);
}

__global__ void __launch_bounds__(256, 1) lstm_scan_wmma(
    const float* __restrict__ xg,    // [S][B][G] gate preacts (no bias)
    const float* __restrict__ Whh,   // [G][H]
    const float* __restrict__ bias1, const float* __restrict__ bias2,
    __nv_bfloat16* __restrict__ hHi, __nv_bfloat16* __restrict__ hLo,
    float* __restrict__ hC,
    float* __restrict__ hist,        // [S][B][H] or nullptr
    int barIdx)
{
    extern __shared__ char sm[];
    __nv_bfloat16* AsmHi = (__nv_bfloat16*)(sm + AHI_OFF);
    __nv_bfloat16* AsmLo = (__nv_bfloat16*)(sm + ALO_OFF);
    __nv_bfloat16* WsmHi = (__nv_bfloat16*)(sm + WRD_OFF);
    __nv_bfloat16* WsmLo = (__nv_bfloat16*)(sm + WRD_OFF + 16 * PW * 2);
    float* part = (float*)(sm + WRD_OFF);      // [8][64][16], reuses W region
    float* gsm  = (float*)(sm + GSM_OFF);      // [16][68]
    float* csm  = (float*)(sm + CSM_OFF);      // [64][4]
    float* bsm  = (float*)(sm + BSM_OFF);      // [16]

    const int tid = threadIdx.x;
    const int wid = tid >> 5;
    const int kb  = wid * 64;                  // this warp's k-range base
    const int u0  = blockIdx.x * 4;
    unsigned* bar = &g_bar[barIdx];
    const unsigned nctas = gridDim.x;

    // ---- prologue: split W rows (g*H + u0 + u) into smem hi/lo --------------
#pragma unroll 4
    for (int i = 0; i < 32; ++i) {
        int idx = tid + i * 256;               // 16 rows x 512 k
        int row = idx >> 9, k = idx & 511;
        int g = row >> 2, u = row & 3;
        float v = Whh[(size_t)(g * Hx + u0 + u) * Hx + k];
        __nv_bfloat16 hi = __float2bfloat16(v);
        WsmHi[row * PW + k] = hi;
        WsmLo[row * PW + k] = __float2bfloat16(v - __bfloat162float(hi));
    }
    if (tid < 16) {
        int g = tid >> 2, u = tid & 3;
        bsm[tid] = bias1[g * Hx + u0 + u] + bias2[g * Hx + u0 + u];
    }
    csm[tid] = 0.f;
    __syncthreads();

    // ---- resident B fragments (W is constant across all steps) --------------
    wmma::fragment<wmma::matrix_b, 16, 16, 16, __nv_bfloat16, wmma::col_major> bfHi[4], bfLo[4];
#pragma unroll
    for (int j = 0; j < 4; ++j) {
        wmma::load_matrix_sync(bfHi[j], WsmHi + kb + j * 16, PW);
        wmma::load_matrix_sync(bfLo[j], WsmLo + kb + j * 16, PW);
    }
    __syncthreads();   // after this, W region becomes the partial-C buffer

    // reduction-thread mapping
    const int rr = tid & 15;                   // gate row 0..15 (r = g*4+u)
    const int bg = tid >> 4;                   // batch group 0..15
    const int rg = rr >> 2, ru = rr & 3;

    for (int s = 0; s < Sx; ++s) {
        // prefetch xg early (L2/DRAM latency hidden under staging+mma)
        float xr[4];
#pragma unroll
        for (int i = 0; i < 4; ++i) {
            int b = bg * 4 + i;
            xr[i] = __ldcg(xg + (size_t)(s * Bx + b) * Gx + rg * Hx + u0 + ru);
        }

        wmma::fragment<wmma::accumulator, 16, 16, 16, float> acc[4];
#pragma unroll
        for (int mt = 0; mt < 4; ++mt) wmma::fill_fragment(acc[mt], 0.f);

        if (s > 0) {
            // stage h_hi [64][512] bf16 -> smem (padded rows)
#pragma unroll
            for (int i = 0; i < 16; ++i) {
                int c = tid + i * 256;
                *(uint4*)((char*)AsmHi + (c >> 6) * (PW * 2) + (c & 63) * 16) =
                    __ldcg((const uint4*)hHi + c);
            }
            __syncthreads();

            // prefetch first half of h_lo while doing hi-pass mma
            uint4 lo0[8];
#pragma unroll
            for (int i = 0; i < 8; ++i)
                lo0[i] = __ldcg((const uint4*)hLo + tid + i * 256);

            wmma::fragment<wmma::matrix_a, 16, 16, 16, __nv_bfloat16, wmma::row_major> af[4];
#pragma unroll
            for (int j = 0; j < 2; ++j) {
                const __nv_bfloat16* ab = AsmHi + kb + j * 16;
#pragma unroll
                for (int mt = 0; mt < 4; ++mt)
                    wmma::load_matrix_sync(af[mt], ab + mt * 16 * PW, PW);
#pragma unroll
                for (int mt = 0; mt < 4; ++mt)
                    wmma::mma_sync(acc[mt], af[mt], bfHi[j], acc[mt]);
#pragma unroll
                for (int mt = 0; mt < 4; ++mt)
                    wmma::mma_sync(acc[mt], af[mt], bfLo[j], acc[mt]);
            }
            // store lo half 1, prefetch lo half 2
#pragma unroll
            for (int i = 0; i < 8; ++i) {
                int c = tid + i * 256;
                *(uint4*)((char*)AsmLo + (c >> 6) * (PW * 2) + (c & 63) * 16) = lo0[i];
            }
            uint4 lo1[8];
#pragma unroll
            for (int i = 0; i < 8; ++i)
                lo1[i] = __ldcg((const uint4*)hLo + tid + (i + 8) * 256);
#pragma unroll
            for (int j = 2; j < 4; ++j) {
                const __nv_bfloat16* ab = AsmHi + kb + j * 16;
#pragma unroll
                for (int mt = 0; mt < 4; ++mt)
                    wmma::load_matrix_sync(af[mt], ab + mt * 16 * PW, PW);
#pragma unroll
                for (int mt = 0; mt < 4; ++mt)
                    wmma::mma_sync(acc[mt], af[mt], bfHi[j], acc[mt]);
#pragma unroll
                for (int mt = 0; mt < 4; ++mt)
                    wmma::mma_sync(acc[mt], af[mt], bfLo[j], acc[mt]);
            }
#pragma unroll
            for (int i = 0; i < 8; ++i) {
                int c = tid + (i + 8) * 256;
                *(uint4*)((char*)AsmLo + (c >> 6) * (PW * 2) + (c & 63) * 16) = lo1[i];
            }
            __syncthreads();

            // lo pass: h_lo * W_hi
#pragma unroll
            for (int j = 0; j < 4; ++j) {
                const __nv_bfloat16* ab = AsmLo + kb + j * 16;
#pragma unroll
                for (int mt = 0; mt < 4; ++mt)
                    wmma::load_matrix_sync(af[mt], ab + mt * 16 * PW, PW);
#pragma unroll
                for (int mt = 0; mt < 4; ++mt)
                    wmma::mma_sync(acc[mt], af[mt], bfHi[j], acc[mt]);
            }

            // partial C -> smem [w][b][r]
#pragma unroll
            for (int mt = 0; mt < 4; ++mt)
                wmma::store_matrix_sync(part + wid * 1024 + mt * 256, acc[mt],
                                        16, wmma::mem_row_major);
        }
        __syncthreads();

        // ---- reduce 8 warps + xg + bias -> gsm[r][b] ------------------------
#pragma unroll
        for (int i = 0; i < 4; ++i) {
            int b = bg * 4 + i;
            float v = xr[i] + bsm[rr];
            if (s > 0) {
#pragma unroll
                for (int w = 0; w < 8; ++w)
                    v += part[w * 1024 + b * 16 + rr];
            }
            gsm[rr * 68 + b] = v;
        }
        __syncthreads();

        // ---- gates + state update (64 threads, one batch each) --------------
        if (tid < 64) {
            const int b = tid;
            float4 cv = *(float4*)&csm[b * 4];
            float c4[4] = {cv.x, cv.y, cv.z, cv.w};
            float h4[4];
#pragma unroll
            for (int u = 0; u < 4; ++u) {
                float ig = sigf(gsm[(0 + u) * 68 + b]);
                float fg = sigf(gsm[(4 + u) * 68 + b]);
                float gg = tanhap(gsm[(8 + u) * 68 + b]);
                float og = sigf(gsm[(12 + u) * 68 + b]);
                c4[u] = fg * c4[u] + ig * gg;
                h4[u] = og * tanhap(c4[u]);
            }
            *(float4*)&csm[b * 4] = make_float4(c4[0], c4[1], c4[2], c4[3]);

            // write h: fp32 current + bf16 hi/lo split, [b][j] layout
            float4 hv = make_float4(h4[0], h4[1], h4[2], h4[3]);
            *(float4*)(hC + (size_t)b * Hx + u0) = hv;
            __nv_bfloat162 hi01, hi23, lo01, lo23;
            {
                __nv_bfloat16 a0 = __float2bfloat16(h4[0]);
                __nv_bfloat16 a1 = __float2bfloat16(h4[1]);
                __nv_bfloat16 a2 = __float2bfloat16(h4[2]);
                __nv_bfloat16 a3 = __float2bfloat16(h4[3]);
                hi01 = __nv_bfloat162(a0, a1); hi23 = __nv_bfloat162(a2, a3);
                lo01 = __nv_bfloat162(__float2bfloat16(h4[0] - __bfloat162float(a0)),
                                      __float2bfloat16(h4[1] - __bfloat162float(a1)));
                lo23 = __nv_bfloat162(__float2bfloat16(h4[2] - __bfloat162float(a2)),
                                      __float2bfloat16(h4[3] - __bfloat162float(a3)));
            }
            *(__nv_bfloat162*)(hHi + (size_t)b * Hx + u0)     = hi01;
            *(__nv_bfloat162*)(hHi + (size_t)b * Hx + u0 + 2) = hi23;
            *(__nv_bfloat162*)(hLo + (size_t)b * Hx + u0)     = lo01;
            *(__nv_bfloat162*)(hLo + (size_t)b * Hx + u0 + 2) = lo23;
            if (hist)
                *(float4*)(hist + (size_t)(s * Bx + b) * Hx + u0) = hv;
        }

        // ---- grid barrier ----------------------------------------------------
        __syncthreads();
        if (tid == 0) {
            __threadfence();
            atomicAdd(bar, 1u);
            unsigned target = nctas * (unsigned)(s + 1);
            while (*((volatile unsigned*)bar) < target) {}
            __threadfence();
        }
        __syncthreads();
    }
}

// ---------------- final FC ---------------------------------------------------
__global__ void fc_kernel(const float* __restrict__ hC, const float* __restrict__ fw,
                          const float* __restrict__ fb, float* __restrict__ out)
{
    __shared__ float hb[Hx];
    int b = blockIdx.x;
    int o = threadIdx.x;
    for (int j = threadIdx.x; j < Hx; j += OUTx) hb[j] = hC[(size_t)b * Hx + j];
    __syncthreads();
    float acc = fb[o];
    const float* wr = fw + (size_t)o * Hx;
#pragma unroll 4
    for (int j = 0; j < Hx; j += 4) {
        float4 w = *(const float4*)(wr + j);
        float4 h = *(const float4*)(hb + j);
        acc += w.x * h.x + w.y * h.y + w.z * h.z + w.w * h.w;
    }
    out[b * OUTx + o] = acc;
}

// ---------------- launch ------------------------------------------------------
extern "C" void kernel_launch(void* const* d_in, const int* in_sizes, int n_in,
                              void* d_out, int out_size)
{
    const float* x    = (const float*)d_in[0];
    const float* Wih0 = (const float*)d_in[1];
    const float* Whh0 = (const float*)d_in[2];
    const float* bih0 = (const float*)d_in[3];
    const float* bhh0 = (const float*)d_in[4];
    const float* Wih1 = (const float*)d_in[5];
    const float* Whh1 = (const float*)d_in[6];
    const float* bih1 = (const float*)d_in[7];
    const float* bhh1 = (const float*)d_in[8];
    const float* fcw  = (const float*)d_in[9];
    const float* fcb  = (const float*)d_in[10];
    float* out = (float*)d_out;

    cudaFuncSetAttribute((const void*)lstm_scan_wmma,
                         cudaFuncAttributeMaxDynamicSharedMemorySize, SCAN2_SMEM);

    void *xg_p, *h1_p, *hC_p, *hHi_p, *hLo_p, *a2_p, *w2_p;
    cudaGetSymbolAddress(&xg_p, g_xg);
    cudaGetSymbolAddress(&h1_p, g_h1);
    cudaGetSymbolAddress(&hC_p, g_hC);
    cudaGetSymbolAddress(&hHi_p, g_hHi);
    cudaGetSymbolAddress(&hLo_p, g_hLo);
    cudaGetSymbolAddress(&a2_p, g_A2);
    cudaGetSymbolAddress(&w2_p, g_W2);

    init_kernel<<<1, 32>>>();

    dim3 mgrid(Gx / 128, (Sx * Bx) / 128);   // (16, 256)

    // ---- layer 0 ----
    conv_w_kernel<<<Gx, 128>>>(Wih0, (__nv_bfloat16*)w2_p, Dx);
    conv_a_kernel<<<Sx * Bx, 128>>>(x, (__nv_bfloat16*)a2_p, Dx, 0);
    wmma_gemm_kernel<<<mgrid, 256>>>(
        (const __nv_bfloat16*)a2_p, (const __nv_bfloat16*)w2_p,
        (float*)xg_p, 3 * Dx);
    lstm_scan_wmma<<<128, 256, SCAN2_SMEM>>>(
        (const float*)xg_p, Whh0, bih0, bhh0,
        (__nv_bfloat16*)hHi_p, (__nv_bfloat16*)hLo_p, (float*)hC_p,
        (float*)h1_p, 0);

    // ---- layer 1 ----
    conv_w_kernel<<<Gx, 128>>>(Wih1, (__nv_bfloat16*)w2_p, Hx);
    conv_a_kernel<<<Sx * Bx, 128>>>((const float*)h1_p, (__nv_bfloat16*)a2_p, Hx, 1);
    wmma_gemm_kernel<<<mgrid, 256>>>(
        (const __nv_bfloat16*)a2_p, (const __nv_bfloat16*)w2_p,
        (float*)xg_p, 3 * Hx);
    lstm_scan_wmma<<<128, 256, SCAN2_SMEM>>>(
        (const float*)xg_p, Whh1, bih1, bhh1,
        (__nv_bfloat16*)hHi_p, (__nv_bfloat16*)hLo_p, (float*)hC_p,
        nullptr, 1);

    fc_kernel<<<Bx, OUTx>>>((const float*)hC_p, fcw, fcb, out);
}

// round 11
// speedup vs baseline: 2.1362x; 1.2588x over previous
#include <cuda_runtime.h>
#include <cuda_bf16.h>
#include <mma.h>
#include <cstdint>
#include <cstddef>

using namespace nvcuda;

#define Bx   64
#define Sx   512
#define Dx   256
#define Hx   512
#define Gx   2048   // 4*H
#define OUTx 128
#define HB   (Bx * Hx)   // 32768

// ---------------- scratch (static device allocations are the allowed path) ---
__device__ float g_xg[(size_t)Sx * Bx * Gx];                 // layer-0 gate preacts (no bias)
__device__ __align__(16) __nv_bfloat16 g_h1Hi[2][HB];        // h1 double-buffered hi/lo
__device__ __align__(16) __nv_bfloat16 g_h1Lo[2][HB];
__device__ __align__(16) __nv_bfloat16 g_h2Hi[2][HB];        // h2 double-buffered hi/lo
__device__ __align__(16) __nv_bfloat16 g_h2Lo[2][HB];
__device__ float g_h2C[HB];                                  // h2 fp32 [b][j] for FC
__device__ unsigned g_bar[1];
__device__ __nv_bfloat16 g_A2[(size_t)Sx * Bx * 3 * Dx];     // split-A for gemm0
__device__ __nv_bfloat16 g_W2[(size_t)Gx * 3 * Dx];          // split-W for gemm0

__global__ void init_kernel() { if (threadIdx.x == 0) g_bar[0] = 0u; }

// ---------------- fp32 -> (hi,lo) bf16 split conversions ---------------------
__global__ void conv_w_kernel(const float* __restrict__ W, __nv_bfloat16* __restrict__ W2, int K)
{
    int n = blockIdx.x;
    const float* src = W + (size_t)n * K;
    __nv_bfloat16* dst = W2 + (size_t)n * 3 * K;
    for (int k = threadIdx.x; k < K; k += blockDim.x) {
        float v = src[k];
        __nv_bfloat16 hi = __float2bfloat16(v);
        __nv_bfloat16 lo = __float2bfloat16(v - __bfloat162float(hi));
        dst[k] = hi; dst[K + k] = lo; dst[2 * K + k] = hi;
    }
}

__global__ void conv_a_kernel(const float* __restrict__ A, __nv_bfloat16* __restrict__ A2, int K)
{
    int m = blockIdx.x;   // m = s*64 + b ; A is x[b][s][k]
    const float* src = A + (size_t)(m & 63) * (Sx * Dx) + (size_t)(m >> 6) * Dx;
    __nv_bfloat16* dst = A2 + (size_t)m * 3 * K;
    for (int k = threadIdx.x; k < K; k += blockDim.x) {
        float v = src[k];
        __nv_bfloat16 hi = __float2bfloat16(v);
        __nv_bfloat16 lo = __float2bfloat16(v - __bfloat162float(hi));
        dst[k] = hi; dst[K + k] = hi; dst[2 * K + k] = lo;
    }
}

// ---------------- HMMA (wmma) GEMM for layer-0 input projection (R9) ---------
#define LDP 40

__global__ void __launch_bounds__(256, 1) wmma_gemm_kernel(
    const __nv_bfloat16* __restrict__ A2, const __nv_bfloat16* __restrict__ W2,
    float* __restrict__ C, int Ktot)
{
    __shared__ __align__(16) __nv_bfloat16 As[2][128 * LDP];
    __shared__ __align__(16) __nv_bfloat16 Bs[2][128 * LDP];

    const int tid = threadIdx.x;
    const int wid = tid >> 5;
    const int m0 = blockIdx.y * 128;
    const int n0 = blockIdx.x * 128;
    const int wm = (wid >> 2) * 64;
    const int wn = (wid & 3) * 32;

    wmma::fragment<wmma::accumulator, 16, 16, 16, float> acc[4][2];
#pragma unroll
    for (int i = 0; i < 4; ++i)
#pragma unroll
        for (int j = 0; j < 2; ++j) wmma::fill_fragment(acc[i][j], 0.f);

    const int ca = tid, cb = tid + 256;
    const int ra = ca >> 2, qa = ca & 3;
    const int rb = cb >> 2, qb = cb & 3;
    const char* Ag = (const char*)A2;
    const char* Bg = (const char*)W2;
    const size_t aoff0 = ((size_t)(m0 + ra) * Ktot + qa * 8) * 2;
    const size_t aoff1 = ((size_t)(m0 + rb) * Ktot + qb * 8) * 2;
    const size_t boff0 = ((size_t)(n0 + ra) * Ktot + qa * 8) * 2;
    const size_t boff1 = ((size_t)(n0 + rb) * Ktot + qb * 8) * 2;
    const int s0 = ra * (LDP * 2) + qa * 16;
    const int s1 = rb * (LDP * 2) + qb * 16;

    {
        uint4 a0 = *(const uint4*)(Ag + aoff0);
        uint4 a1 = *(const uint4*)(Ag + aoff1);
        uint4 b0 = *(const uint4*)(Bg + boff0);
        uint4 b1 = *(const uint4*)(Bg + boff1);
        *(uint4*)((char*)As[0] + s0) = a0;
        *(uint4*)((char*)As[0] + s1) = a1;
        *(uint4*)((char*)Bs[0] + s0) = b0;
        *(uint4*)((char*)Bs[0] + s1) = b1;
    }
    __syncthreads();

    const int T = Ktot >> 5;
    for (int t = 0; t < T; ++t) {
        const int buf = t & 1;
        const bool more = (t + 1 < T);
        uint4 na0, na1, nb0, nb1;
        if (more) {
            size_t ko = (size_t)(t + 1) * 64;
            na0 = *(const uint4*)(Ag + aoff0 + ko);
            na1 = *(const uint4*)(Ag + aoff1 + ko);
            nb0 = *(const uint4*)(Bg + boff0 + ko);
            nb1 = *(const uint4*)(Bg + boff1 + ko);
        }
#pragma unroll
        for (int ks = 0; ks < 2; ++ks) {
            wmma::fragment<wmma::matrix_a, 16, 16, 16, __nv_bfloat16, wmma::row_major> af[4];
            wmma::fragment<wmma::matrix_b, 16, 16, 16, __nv_bfloat16, wmma::col_major> bf[2];
#pragma unroll
            for (int i = 0; i < 4; ++i)
                wmma::load_matrix_sync(af[i], &As[buf][(wm + i * 16) * LDP + ks * 16], LDP);
#pragma unroll
            for (int j = 0; j < 2; ++j)
                wmma::load_matrix_sync(bf[j], &Bs[buf][(wn + j * 16) * LDP + ks * 16], LDP);
#pragma unroll
            for (int i = 0; i < 4; ++i)
#pragma unroll
                for (int j = 0; j < 2; ++j)
                    wmma::mma_sync(acc[i][j], af[i], bf[j], acc[i][j]);
        }
        if (more) {
            const int nb = buf ^ 1;
            *(uint4*)((char*)As[nb] + s0) = na0;
            *(uint4*)((char*)As[nb] + s1) = na1;
            *(uint4*)((char*)Bs[nb] + s0) = nb0;
            *(uint4*)((char*)Bs[nb] + s1) = nb1;
            __syncthreads();
        }
    }

#pragma unroll
    for (int i = 0; i < 4; ++i)
#pragma unroll
        for (int j = 0; j < 2; ++j)
            wmma::store_matrix_sync(
                C + (size_t)(m0 + wm + i * 16) * Gx + n0 + wn + j * 16,
                acc[i][j], Gx, wmma::mem_row_major);
}

// ---------------- fused 2-layer pipelined LSTM scan ---------------------------
// 128 CTAs: [0,64) layer 0, [64,128) layer 1. 32 gate rows (8 units) per CTA.
// Tick t: L0 computes step t; L1 computes step t-1 (consumes h1[t-1]).
// L1's K=1024 = [Wih1 ; Whh1] concatenation — xg1 never materialized.
#define PWE   520                       // padded k-stride (elems) for A/W smem tiles
#define SM_AHI 0
#define SM_ALO 66560
#define SM_WLO 133120                   // L1: resident W-lo [2][32][520]
#define SM_GSM 199680                   // [32][65] floats
#define SM_CSM 208000                   // [64][9]  floats
#define SM_BSM 210304                   // [32]     floats
#define FUSED_SMEM 210432

typedef wmma::fragment<wmma::matrix_a, 16, 16, 16, __nv_bfloat16, wmma::row_major> frag_a;
typedef wmma::fragment<wmma::matrix_b, 16, 16, 16, __nv_bfloat16, wmma::col_major> frag_b;
typedef wmma::fragment<wmma::accumulator, 16, 16, 16, float> frag_c;

__device__ __forceinline__ float tanhap(float x) {
    float y; asm("tanh.approx.f32 %0, %1;" : "=f"(y) : "f"(x)); return y;
}
__device__ __forceinline__ float sigf(float x) {
    return fmaf(tanhap(x * 0.5f), 0.5f, 0.5f);
}

// stage 64x512 bf16 [b][j] from global into padded smem tile (row stride 1040 B)
__device__ __forceinline__ void stage64(char* dst, const __nv_bfloat16* src, int tid) {
#pragma unroll
    for (int i = 0; i < 16; ++i) {
        int c = tid + i * 256;                     // 4096 16B-chunks
        int row = c >> 6, col = c & 63;
        uint4 v = __ldcg((const uint4*)(src + row * Hx) + col);
        *(uint4*)(dst + row * 1040 + col * 16) = v;
    }
}

__device__ __forceinline__ void gridbar(unsigned* bar, int t, int tid) {
    __syncthreads();
    if (tid == 0) {
        __threadfence();
        atomicAdd(bar, 1u);
        unsigned target = 128u * (unsigned)(t + 1);
        while (*((volatile unsigned*)bar) < target) {}
        __threadfence();
    }
    __syncthreads();
}

template<bool L1P>
__device__ void scan_layer(const float* xg, const float* Wk0, const float* Wk1,
                           const float* b1, const float* b2, char* sm, int cta)
{
    constexpr int NKH = L1P ? 2 : 1;
    const int tid = threadIdx.x;
    const int wid = tid >> 5;
    const int u0  = cta * 8;
    __nv_bfloat16* AsmHi = (__nv_bfloat16*)(sm + SM_AHI);
    __nv_bfloat16* AsmLo = (__nv_bfloat16*)(sm + SM_ALO);
    __nv_bfloat16* WloS  = (__nv_bfloat16*)(sm + SM_WLO);
    float* gsm = (float*)(sm + SM_GSM);
    float* csm = (float*)(sm + SM_CSM);
    float* bsm = (float*)(sm + SM_BSM);
    float* P   = (float*)(sm + SM_AHI);            // partial buffer aliases Asm

    // ---- prologue: split W and make hi-fragments resident --------------------
    frag_b whi[NKH][4][2];
    frag_b wloR[4][2];                             // resident W-lo (L0 only)
    const int kb = wid * 64;
#pragma unroll
    for (int kh = 0; kh < NKH; ++kh) {
        const float* Wsrc = (kh == 0) ? Wk0 : Wk1;
        __nv_bfloat16* loDst = L1P ? (WloS + kh * 32 * PWE) : AsmLo;
#pragma unroll 4
        for (int i = 0; i < 64; ++i) {
            int idx = tid + i * 256;               // 32 rows x 512 k
            int r = idx >> 9, k = idx & 511;
            float v = Wsrc[(size_t)((r >> 3) * Hx + u0 + (r & 7)) * Hx + k];
            __nv_bfloat16 hi = __float2bfloat16(v);
            AsmHi[r * PWE + k] = hi;
            loDst[r * PWE + k] = __float2bfloat16(v - __bfloat162float(hi));
        }
        __syncthreads();
#pragma unroll
        for (int j = 0; j < 4; ++j)
#pragma unroll
            for (int rt = 0; rt < 2; ++rt) {
                wmma::load_matrix_sync(whi[kh][j][rt],
                    AsmHi + rt * 16 * PWE + kb + j * 16, PWE);
                if (!L1P)
                    wmma::load_matrix_sync(wloR[j][rt],
                        AsmLo + rt * 16 * PWE + kb + j * 16, PWE);
            }
        __syncthreads();
    }
    if (tid < 32)
        bsm[tid] = b1[(tid >> 3) * Hx + u0 + (tid & 7)] +
                   b2[(tid >> 3) * Hx + u0 + (tid & 7)];
    if (tid < 64) {
#pragma unroll
        for (int u = 0; u < 8; ++u) csm[tid * 9 + u] = 0.f;
    }
    __syncthreads();

    // ---- main pipeline loop: 513 ticks ---------------------------------------
    for (int t = 0; t <= Sx; ++t) {
        const int  s      = L1P ? (t - 1) : t;
        const bool active = L1P ? (t >= 1) : (t < Sx);
        if (active) {
            // gsm init: xg+bias (L0) / bias (L1)
            if (!L1P) {
                int b = tid >> 2, grp = tid & 3;
                const float* xp = xg + ((size_t)(s * Bx + b)) * Gx + grp * Hx + u0;
                float4 v0 = __ldcg((const float4*)xp);
                float4 v1 = __ldcg((const float4*)(xp + 4));
                float xv[8] = {v0.x, v0.y, v0.z, v0.w, v1.x, v1.y, v1.z, v1.w};
#pragma unroll
                for (int uu = 0; uu < 8; ++uu)
                    gsm[(grp * 8 + uu) * 65 + b] = xv[uu] + bsm[grp * 8 + uu];
            } else {
#pragma unroll
                for (int i = 0; i < 8; ++i) {
                    int cell = tid + i * 256;
                    gsm[(cell & 31) * 65 + (cell >> 5)] = bsm[cell & 31];
                }
            }

            const bool doMMA = L1P || (s > 0);
            const int  nkh   = (!L1P) ? 1 : ((s > 0) ? 2 : 1);
            if (doMMA) {
                frag_c acc[4][2];
#pragma unroll
                for (int mt = 0; mt < 4; ++mt)
#pragma unroll
                    for (int rt = 0; rt < 2; ++rt)
                        wmma::fill_fragment(acc[mt][rt], 0.f);

#pragma unroll
                for (int kh = 0; kh < NKH; ++kh) {
                    if (kh >= nkh) break;
                    const __nv_bfloat16 *srcHi, *srcLo;
                    if (!L1P)        { srcHi = g_h1Hi[(s - 1) & 1]; srcLo = g_h1Lo[(s - 1) & 1]; }
                    else if (kh == 0){ srcHi = g_h1Hi[s & 1];       srcLo = g_h1Lo[s & 1]; }
                    else             { srcHi = g_h2Hi[(s - 1) & 1]; srcLo = g_h2Lo[(s - 1) & 1]; }
                    stage64(sm + SM_AHI, srcHi, tid);
                    stage64(sm + SM_ALO, srcLo, tid);
                    __syncthreads();
                    // pass 1+2: Ahi x (Whi, Wlo)
#pragma unroll
                    for (int j = 0; j < 4; ++j) {
                        frag_a ah[4];
#pragma unroll
                        for (int mt = 0; mt < 4; ++mt)
                            wmma::load_matrix_sync(ah[mt],
                                AsmHi + mt * 16 * PWE + kb + j * 16, PWE);
#pragma unroll
                        for (int rt = 0; rt < 2; ++rt) {
#pragma unroll
                            for (int mt = 0; mt < 4; ++mt)
                                wmma::mma_sync(acc[mt][rt], ah[mt], whi[kh][j][rt], acc[mt][rt]);
                            if (L1P) {
                                frag_b wl;
                                wmma::load_matrix_sync(wl,
                                    WloS + kh * 32 * PWE + rt * 16 * PWE + kb + j * 16, PWE);
#pragma unroll
                                for (int mt = 0; mt < 4; ++mt)
                                    wmma::mma_sync(acc[mt][rt], ah[mt], wl, acc[mt][rt]);
                            } else {
#pragma unroll
                                for (int mt = 0; mt < 4; ++mt)
                                    wmma::mma_sync(acc[mt][rt], ah[mt], wloR[j][rt], acc[mt][rt]);
                            }
                        }
                    }
                    // pass 3: Alo x Whi
#pragma unroll
                    for (int j = 0; j < 4; ++j) {
                        frag_a al[4];
#pragma unroll
                        for (int mt = 0; mt < 4; ++mt)
                            wmma::load_matrix_sync(al[mt],
                                AsmLo + mt * 16 * PWE + kb + j * 16, PWE);
#pragma unroll
                        for (int rt = 0; rt < 2; ++rt)
#pragma unroll
                            for (int mt = 0; mt < 4; ++mt)
                                wmma::mma_sync(acc[mt][rt], al[mt], whi[kh][j][rt], acc[mt][rt]);
                    }
                    __syncthreads();
                }
                // partial store (aliases Asm; all reads finished above)
#pragma unroll
                for (int mt = 0; mt < 4; ++mt)
#pragma unroll
                    for (int rt = 0; rt < 2; ++rt)
                        wmma::store_matrix_sync(P + wid * 2304 + mt * 16 * 36 + rt * 16,
                                                acc[mt][rt], 36, wmma::mem_row_major);
                __syncthreads();
                // 8-way reduce into gsm
#pragma unroll
                for (int i = 0; i < 8; ++i) {
                    int cell = tid + i * 256;
                    int b = cell >> 5, r = cell & 31;
                    float v = 0.f;
#pragma unroll
                    for (int w = 0; w < 8; ++w) v += P[w * 2304 + b * 36 + r];
                    gsm[r * 65 + b] += v;
                }
            }
            __syncthreads();
            // gates + state update (64 threads, one batch each, 8 units)
            if (tid < 64) {
                const int b = tid;
                float hv[8];
#pragma unroll
                for (int u = 0; u < 8; ++u) {
                    float ig = sigf(gsm[u * 65 + b]);
                    float fg = sigf(gsm[(8 + u) * 65 + b]);
                    float gg = tanhap(gsm[(16 + u) * 65 + b]);
                    float og = sigf(gsm[(24 + u) * 65 + b]);
                    float c  = csm[b * 9 + u];
                    c = fg * c + ig * gg;
                    csm[b * 9 + u] = c;
                    hv[u] = og * tanhap(c);
                }
                __nv_bfloat162 hp[4], lp[4];
#pragma unroll
                for (int q = 0; q < 4; ++q) {
                    __nv_bfloat16 a0 = __float2bfloat16(hv[2 * q]);
                    __nv_bfloat16 a1 = __float2bfloat16(hv[2 * q + 1]);
                    hp[q] = __nv_bfloat162(a0, a1);
                    lp[q] = __nv_bfloat162(
                        __float2bfloat16(hv[2 * q]     - __bfloat162float(a0)),
                        __float2bfloat16(hv[2 * q + 1] - __bfloat162float(a1)));
                }
                __nv_bfloat16* dH = (L1P ? g_h2Hi[s & 1] : g_h1Hi[s & 1]) + b * Hx + u0;
                __nv_bfloat16* dL = (L1P ? g_h2Lo[s & 1] : g_h1Lo[s & 1]) + b * Hx + u0;
                *(uint4*)dH = *(uint4*)hp;
                *(uint4*)dL = *(uint4*)lp;
                if (L1P) {
                    float4 f0 = make_float4(hv[0], hv[1], hv[2], hv[3]);
                    float4 f1 = make_float4(hv[4], hv[5], hv[6], hv[7]);
                    *(float4*)(g_h2C + b * Hx + u0)     = f0;
                    *(float4*)(g_h2C + b * Hx + u0 + 4) = f1;
                }
            }
        }
        gridbar(g_bar, t, tid);
    }
}

__global__ void __launch_bounds__(256, 1) fused_scan(
    const float* __restrict__ xg,
    const float* __restrict__ Whh0, const float* __restrict__ Wih1,
    const float* __restrict__ Whh1,
    const float* __restrict__ bih0, const float* __restrict__ bhh0,
    const float* __restrict__ bih1, const float* __restrict__ bhh1)
{
    extern __shared__ char sm[];
    const int c = blockIdx.x;
    if (c < 64)
        scan_layer<false>(xg, Whh0, nullptr, bih0, bhh0, sm, c);
    else
        scan_layer<true>(nullptr, Wih1, Whh1, bih1, bhh1, sm, c - 64);
}

// ---------------- final FC ---------------------------------------------------
__global__ void fc_kernel(const float* __restrict__ hC, const float* __restrict__ fw,
                          const float* __restrict__ fb, float* __restrict__ out)
{
    __shared__ float hb[Hx];
    int b = blockIdx.x;
    int o = threadIdx.x;
    for (int j = threadIdx.x; j < Hx; j += OUTx) hb[j] = hC[(size_t)b * Hx + j];
    __syncthreads();
    float acc = fb[o];
    const float* wr = fw + (size_t)o * Hx;
#pragma unroll 4
    for (int j = 0; j < Hx; j += 4) {
        float4 w = *(const float4*)(wr + j);
        float4 h = *(const float4*)(hb + j);
        acc += w.x * h.x + w.y * h.y + w.z * h.z + w.w * h.w;
    }
    out[b * OUTx + o] = acc;
}

// ---------------- launch ------------------------------------------------------
extern "C" void kernel_launch(void* const* d_in, const int* in_sizes, int n_in,
                              void* d_out, int out_size)
{
    const float* x    = (const float*)d_in[0];
    const float* Wih0 = (const float*)d_in[1];
    const float* Whh0 = (const float*)d_in[2];
    const float* bih0 = (const float*)d_in[3];
    const float* bhh0 = (const float*)d_in[4];
    const float* Wih1 = (const float*)d_in[5];
    const float* Whh1 = (const float*)d_in[6];
    const float* bih1 = (const float*)d_in[7];
    const float* bhh1 = (const float*)d_in[8];
    const float* fcw  = (const float*)d_in[9];
    const float* fcb  = (const float*)d_in[10];
    float* out = (float*)d_out;

    cudaFuncSetAttribute((const void*)fused_scan,
                         cudaFuncAttributeMaxDynamicSharedMemorySize, FUSED_SMEM);

    void *xg_p, *a2_p, *w2_p, *h2c_p;
    cudaGetSymbolAddress(&xg_p, g_xg);
    cudaGetSymbolAddress(&a2_p, g_A2);
    cudaGetSymbolAddress(&w2_p, g_W2);
    cudaGetSymbolAddress(&h2c_p, g_h2C);

    init_kernel<<<1, 32>>>();

    // layer-0 input projection on tensor cores (split-bf16, 3-pass)
    conv_w_kernel<<<Gx, 128>>>(Wih0, (__nv_bfloat16*)w2_p, Dx);
    conv_a_kernel<<<Sx * Bx, 128>>>(x, (__nv_bfloat16*)a2_p, Dx);
    dim3 mgrid(Gx / 128, (Sx * Bx) / 128);   // (16, 256)
    wmma_gemm_kernel<<<mgrid, 256>>>(
        (const __nv_bfloat16*)a2_p, (const __nv_bfloat16*)w2_p,
        (float*)xg_p, 3 * Dx);

    // fused 2-layer pipelined scan (513 ticks, 128 persistent CTAs)
    fused_scan<<<128, 256, FUSED_SMEM>>>(
        (const float*)xg_p, Whh0, Wih1, Whh1, bih0, bhh0, bih1, bhh1);

    fc_kernel<<<Bx, OUTx>>>((const float*)h2c_p, fcw, fcb, out);
}

// round 12
// speedup vs baseline: 2.4074x; 1.1270x over previous
#include <cuda_runtime.h>
#include <cuda_bf16.h>
#include <mma.h>
#include <cstdint>
#include <cstddef>

using namespace nvcuda;

#define Bx   64
#define Sx   512
#define Dx   256
#define Hx   512
#define Gx   2048   // 4*H
#define OUTx 128
#define HB   (Bx * Hx)   // 32768

// ---------------- scratch (static device allocations are the allowed path) ---
__device__ float g_xg[(size_t)Sx * Bx * Gx];                 // layer-0 gate preacts (no bias)
__device__ __align__(16) __nv_bfloat16 g_h1Hi[2][HB];        // h1 double-buffered hi/lo
__device__ __align__(16) __nv_bfloat16 g_h1Lo[2][HB];
__device__ __align__(16) __nv_bfloat16 g_h2Hi[2][HB];        // h2 double-buffered hi/lo
__device__ __align__(16) __nv_bfloat16 g_h2Lo[2][HB];
__device__ float g_h2C[HB];                                  // h2 fp32 [b][j] for FC
__device__ unsigned g_bar[1];
__device__ __nv_bfloat16 g_A2[(size_t)Sx * Bx * 3 * Dx];     // split-A for gemm0
__device__ __nv_bfloat16 g_W2[(size_t)Gx * 3 * Dx];          // split-W for gemm0

__global__ void init_kernel() { if (threadIdx.x == 0) g_bar[0] = 0u; }

// ---------------- fp32 -> (hi,lo) bf16 split conversions ---------------------
__global__ void conv_w_kernel(const float* __restrict__ W, __nv_bfloat16* __restrict__ W2, int K)
{
    int n = blockIdx.x;
    const float* src = W + (size_t)n * K;
    __nv_bfloat16* dst = W2 + (size_t)n * 3 * K;
    for (int k = threadIdx.x; k < K; k += blockDim.x) {
        float v = src[k];
        __nv_bfloat16 hi = __float2bfloat16(v);
        __nv_bfloat16 lo = __float2bfloat16(v - __bfloat162float(hi));
        dst[k] = hi; dst[K + k] = lo; dst[2 * K + k] = hi;
    }
}

__global__ void conv_a_kernel(const float* __restrict__ A, __nv_bfloat16* __restrict__ A2, int K)
{
    int m = blockIdx.x;   // m = s*64 + b ; A is x[b][s][k]
    const float* src = A + (size_t)(m & 63) * (Sx * Dx) + (size_t)(m >> 6) * Dx;
    __nv_bfloat16* dst = A2 + (size_t)m * 3 * K;
    for (int k = threadIdx.x; k < K; k += blockDim.x) {
        float v = src[k];
        __nv_bfloat16 hi = __float2bfloat16(v);
        __nv_bfloat16 lo = __float2bfloat16(v - __bfloat162float(hi));
        dst[k] = hi; dst[K + k] = hi; dst[2 * K + k] = lo;
    }
}

// ---------------- HMMA (wmma) GEMM for layer-0 input projection ---------------
#define LDP 40

__global__ void __launch_bounds__(256, 1) wmma_gemm_kernel(
    const __nv_bfloat16* __restrict__ A2, const __nv_bfloat16* __restrict__ W2,
    float* __restrict__ C, int Ktot)
{
    __shared__ __align__(16) __nv_bfloat16 As[2][128 * LDP];
    __shared__ __align__(16) __nv_bfloat16 Bs[2][128 * LDP];

    const int tid = threadIdx.x;
    const int wid = tid >> 5;
    const int m0 = blockIdx.y * 128;
    const int n0 = blockIdx.x * 128;
    const int wm = (wid >> 2) * 64;
    const int wn = (wid & 3) * 32;

    wmma::fragment<wmma::accumulator, 16, 16, 16, float> acc[4][2];
#pragma unroll
    for (int i = 0; i < 4; ++i)
#pragma unroll
        for (int j = 0; j < 2; ++j) wmma::fill_fragment(acc[i][j], 0.f);

    const int ca = tid, cb = tid + 256;
    const int ra = ca >> 2, qa = ca & 3;
    const int rb = cb >> 2, qb = cb & 3;
    const char* Ag = (const char*)A2;
    const char* Bg = (const char*)W2;
    const size_t aoff0 = ((size_t)(m0 + ra) * Ktot + qa * 8) * 2;
    const size_t aoff1 = ((size_t)(m0 + rb) * Ktot + qb * 8) * 2;
    const size_t boff0 = ((size_t)(n0 + ra) * Ktot + qa * 8) * 2;
    const size_t boff1 = ((size_t)(n0 + rb) * Ktot + qb * 8) * 2;
    const int s0 = ra * (LDP * 2) + qa * 16;
    const int s1 = rb * (LDP * 2) + qb * 16;

    {
        uint4 a0 = *(const uint4*)(Ag + aoff0);
        uint4 a1 = *(const uint4*)(Ag + aoff1);
        uint4 b0 = *(const uint4*)(Bg + boff0);
        uint4 b1 = *(const uint4*)(Bg + boff1);
        *(uint4*)((char*)As[0] + s0) = a0;
        *(uint4*)((char*)As[0] + s1) = a1;
        *(uint4*)((char*)Bs[0] + s0) = b0;
        *(uint4*)((char*)Bs[0] + s1) = b1;
    }
    __syncthreads();

    const int T = Ktot >> 5;
    for (int t = 0; t < T; ++t) {
        const int buf = t & 1;
        const bool more = (t + 1 < T);
        uint4 na0, na1, nb0, nb1;
        if (more) {
            size_t ko = (size_t)(t + 1) * 64;
            na0 = *(const uint4*)(Ag + aoff0 + ko);
            na1 = *(const uint4*)(Ag + aoff1 + ko);
            nb0 = *(const uint4*)(Bg + boff0 + ko);
            nb1 = *(const uint4*)(Bg + boff1 + ko);
        }
#pragma unroll
        for (int ks = 0; ks < 2; ++ks) {
            wmma::fragment<wmma::matrix_a, 16, 16, 16, __nv_bfloat16, wmma::row_major> af[4];
            wmma::fragment<wmma::matrix_b, 16, 16, 16, __nv_bfloat16, wmma::col_major> bf[2];
#pragma unroll
            for (int i = 0; i < 4; ++i)
                wmma::load_matrix_sync(af[i], &As[buf][(wm + i * 16) * LDP + ks * 16], LDP);
#pragma unroll
            for (int j = 0; j < 2; ++j)
                wmma::load_matrix_sync(bf[j], &Bs[buf][(wn + j * 16) * LDP + ks * 16], LDP);
#pragma unroll
            for (int i = 0; i < 4; ++i)
#pragma unroll
                for (int j = 0; j < 2; ++j)
                    wmma::mma_sync(acc[i][j], af[i], bf[j], acc[i][j]);
        }
        if (more) {
            const int nb = buf ^ 1;
            *(uint4*)((char*)As[nb] + s0) = na0;
            *(uint4*)((char*)As[nb] + s1) = na1;
            *(uint4*)((char*)Bs[nb] + s0) = nb0;
            *(uint4*)((char*)Bs[nb] + s1) = nb1;
            __syncthreads();
        }
    }

#pragma unroll
    for (int i = 0; i < 4; ++i)
#pragma unroll
        for (int j = 0; j < 2; ++j)
            wmma::store_matrix_sync(
                C + (size_t)(m0 + wm + i * 16) * Gx + n0 + wn + j * 16,
                acc[i][j], Gx, wmma::mem_row_major);
}

// ---------------- balanced fused 2-layer pipelined LSTM scan ------------------
// 128 identical CTAs; each owns 4 hidden units of BOTH layers (16 gate rows per
// layer). Tick t: L0 step t, L1 step t-1. h1[t-1] staged ONCE per CTA and its
// A-fragments shared between L0 (x W0hh) and L1-kh0 (x W1ih). 3-pass split-bf16.
#define PWE    520
#define SM_AHI 0
#define SM_ALO 66560
#define SM_WLO 133120                  // [3][16][520] bf16 W-lo tiles (resident)
#define SM_GSM 183040                  // [32][65] floats
#define SM_CSM 191360                  // [2][64][4] floats
#define SM_BSM 193408                  // [32] floats
#define FUSED_SMEM 193664

typedef wmma::fragment<wmma::matrix_a, 16, 16, 16, __nv_bfloat16, wmma::row_major> frag_a;
typedef wmma::fragment<wmma::matrix_b, 16, 16, 16, __nv_bfloat16, wmma::col_major> frag_b;
typedef wmma::fragment<wmma::accumulator, 16, 16, 16, float> frag_c;

__device__ __forceinline__ float tanhap(float x) {
    float y; asm("tanh.approx.f32 %0, %1;" : "=f"(y) : "f"(x)); return y;
}
__device__ __forceinline__ float sigf(float x) {
    return fmaf(tanhap(x * 0.5f), 0.5f, 0.5f);
}

__device__ __forceinline__ void stage64(char* dst, const __nv_bfloat16* src, int tid) {
#pragma unroll
    for (int i = 0; i < 16; ++i) {
        int c = tid + i * 256;
        int row = c >> 6, col = c & 63;
        uint4 v = __ldcg((const uint4*)(src + row * Hx) + col);
        *(uint4*)(dst + row * 1040 + col * 16) = v;
    }
}

__global__ void __launch_bounds__(256, 1) fused_scan(
    const float* __restrict__ xg,
    const float* __restrict__ Whh0, const float* __restrict__ Wih1,
    const float* __restrict__ Whh1,
    const float* __restrict__ bih0, const float* __restrict__ bhh0,
    const float* __restrict__ bih1, const float* __restrict__ bhh1)
{
    extern __shared__ char sm[];
    __nv_bfloat16* AsmHi = (__nv_bfloat16*)(sm + SM_AHI);
    __nv_bfloat16* AsmLo = (__nv_bfloat16*)(sm + SM_ALO);
    __nv_bfloat16* WloS  = (__nv_bfloat16*)(sm + SM_WLO);
    float* gsm = (float*)(sm + SM_GSM);
    float* csm = (float*)(sm + SM_CSM);
    float* bsm = (float*)(sm + SM_BSM);
    float* P   = (float*)(sm + SM_AHI);            // partials alias A region

    const int tid = threadIdx.x;
    const int wid = tid >> 5;
    const int kb  = wid * 64;
    const int u0  = blockIdx.x * 4;
    unsigned* bar = g_bar;

    // ---- prologue: split 3 W matrices; hi-frags resident, lo tiles in smem ---
    frag_b whi[3][4];
    const float* Wsrcs[3] = {Whh0, Wih1, Whh1};
#pragma unroll
    for (int m = 0; m < 3; ++m) {
        const float* Wsrc = Wsrcs[m];
        __nv_bfloat16* loT = WloS + m * 16 * PWE;
#pragma unroll 4
        for (int i = 0; i < 32; ++i) {
            int idx = tid + i * 256;               // 16 rows x 512 k
            int r = idx >> 9, k = idx & 511;
            float v = Wsrc[(size_t)((r >> 2) * Hx + u0 + (r & 3)) * Hx + k];
            __nv_bfloat16 hi = __float2bfloat16(v);
            AsmHi[r * PWE + k] = hi;
            loT[r * PWE + k] = __float2bfloat16(v - __bfloat162float(hi));
        }
        __syncthreads();
#pragma unroll
        for (int j = 0; j < 4; ++j)
            wmma::load_matrix_sync(whi[m][j], AsmHi + kb + j * 16, PWE);
        __syncthreads();
    }
    if (tid < 32) {
        int g = (tid >> 2) & 3, u = tid & 3;
        bsm[tid] = (tid < 16)
            ? (bih0[g * Hx + u0 + u] + bhh0[g * Hx + u0 + u])
            : (bih1[g * Hx + u0 + u] + bhh1[g * Hx + u0 + u]);
    }
    if (tid < 128) {
#pragma unroll
        for (int u = 0; u < 4; ++u) csm[tid * 4 + u] = 0.f;  // [2][64][4] flat
    }
    __syncthreads();

    // ---- main pipeline loop: 513 ticks ---------------------------------------
    for (int t = 0; t <= Sx; ++t) {
        const bool l0 = (t < Sx);
        const bool l1 = (t >= 1);

        // prefetch xg for L0 gate threads
        float4 xf0, xf1, xf2, xf3;
        if (l0 && tid < 64) {
            const float* xp = xg + ((size_t)(t * Bx + tid)) * Gx + u0;
            xf0 = __ldcg((const float4*)(xp));
            xf1 = __ldcg((const float4*)(xp + Hx));
            xf2 = __ldcg((const float4*)(xp + 2 * Hx));
            xf3 = __ldcg((const float4*)(xp + 3 * Hx));
        }

        frag_c aL0[4], aL1[4];
#pragma unroll
        for (int mt = 0; mt < 4; ++mt) {
            wmma::fill_fragment(aL0[mt], 0.f);
            wmma::fill_fragment(aL1[mt], 0.f);
        }

        if (t >= 1) {
            // ---- block A: h1[t-1], shared by L0 and L1-kh0 ------------------
            stage64(sm + SM_AHI, g_h1Hi[(t - 1) & 1], tid);
            stage64(sm + SM_ALO, g_h1Lo[(t - 1) & 1], tid);
            __syncthreads();
#pragma unroll
            for (int j = 0; j < 4; ++j) {
                frag_a ah[4];
#pragma unroll
                for (int mt = 0; mt < 4; ++mt)
                    wmma::load_matrix_sync(ah[mt], AsmHi + mt * 16 * PWE + kb + j * 16, PWE);
                if (l0) {
#pragma unroll
                    for (int mt = 0; mt < 4; ++mt)
                        wmma::mma_sync(aL0[mt], ah[mt], whi[0][j], aL0[mt]);
                    frag_b wl0;
                    wmma::load_matrix_sync(wl0, WloS + 0 * 16 * PWE + kb + j * 16, PWE);
#pragma unroll
                    for (int mt = 0; mt < 4; ++mt)
                        wmma::mma_sync(aL0[mt], ah[mt], wl0, aL0[mt]);
                }
#pragma unroll
                for (int mt = 0; mt < 4; ++mt)
                    wmma::mma_sync(aL1[mt], ah[mt], whi[1][j], aL1[mt]);
                {
                    frag_b wl1;
                    wmma::load_matrix_sync(wl1, WloS + 1 * 16 * PWE + kb + j * 16, PWE);
#pragma unroll
                    for (int mt = 0; mt < 4; ++mt)
                        wmma::mma_sync(aL1[mt], ah[mt], wl1, aL1[mt]);
                }
                frag_a al[4];
#pragma unroll
                for (int mt = 0; mt < 4; ++mt)
                    wmma::load_matrix_sync(al[mt], AsmLo + mt * 16 * PWE + kb + j * 16, PWE);
                if (l0) {
#pragma unroll
                    for (int mt = 0; mt < 4; ++mt)
                        wmma::mma_sync(aL0[mt], al[mt], whi[0][j], aL0[mt]);
                }
#pragma unroll
                for (int mt = 0; mt < 4; ++mt)
                    wmma::mma_sync(aL1[mt], al[mt], whi[1][j], aL1[mt]);
            }
            __syncthreads();
        }
        if (t >= 2) {
            // ---- block B: h2[t-2] for L1-kh1 ---------------------------------
            stage64(sm + SM_AHI, g_h2Hi[t & 1], tid);      // (t-2)&1 == t&1
            stage64(sm + SM_ALO, g_h2Lo[t & 1], tid);
            __syncthreads();
#pragma unroll
            for (int j = 0; j < 4; ++j) {
                frag_a ah[4];
#pragma unroll
                for (int mt = 0; mt < 4; ++mt)
                    wmma::load_matrix_sync(ah[mt], AsmHi + mt * 16 * PWE + kb + j * 16, PWE);
#pragma unroll
                for (int mt = 0; mt < 4; ++mt)
                    wmma::mma_sync(aL1[mt], ah[mt], whi[2][j], aL1[mt]);
                {
                    frag_b wl2;
                    wmma::load_matrix_sync(wl2, WloS + 2 * 16 * PWE + kb + j * 16, PWE);
#pragma unroll
                    for (int mt = 0; mt < 4; ++mt)
                        wmma::mma_sync(aL1[mt], ah[mt], wl2, aL1[mt]);
                }
                frag_a al[4];
#pragma unroll
                for (int mt = 0; mt < 4; ++mt)
                    wmma::load_matrix_sync(al[mt], AsmLo + mt * 16 * PWE + kb + j * 16, PWE);
#pragma unroll
                for (int mt = 0; mt < 4; ++mt)
                    wmma::mma_sync(aL1[mt], al[mt], whi[2][j], aL1[mt]);
            }
            __syncthreads();
        }

        if (t >= 1) {
            // partial store: P[w][64b][36]: cols 0..15 = L0 rows, 16..31 = L1
#pragma unroll
            for (int mt = 0; mt < 4; ++mt) {
                wmma::store_matrix_sync(P + wid * 2304 + mt * 16 * 36, aL0[mt],
                                        36, wmma::mem_row_major);
                wmma::store_matrix_sync(P + wid * 2304 + mt * 16 * 36 + 16, aL1[mt],
                                        36, wmma::mem_row_major);
            }
            __syncthreads();
            // 8-way reduce into gsm[32r][65]
#pragma unroll
            for (int i = 0; i < 8; ++i) {
                int cell = tid + i * 256;
                int b = cell >> 5, r = cell & 31;
                float v = 0.f;
#pragma unroll
                for (int w = 0; w < 8; ++w) v += P[w * 2304 + b * 36 + r];
                gsm[r * 65 + b] = v;
            }
            __syncthreads();
        }

        // ---- gates: tid<64 -> L0 batch b, 64..127 -> L1 batch b-64 ----------
        if (tid < 64 && l0) {
            const int b = tid;
            float pre[4][4];   // [gate][unit]
#pragma unroll
            for (int u = 0; u < 4; ++u) {
                pre[0][u] = (t >= 1 ? gsm[(0  + u) * 65 + b] : 0.f) + bsm[0  + u];
                pre[1][u] = (t >= 1 ? gsm[(4  + u) * 65 + b] : 0.f) + bsm[4  + u];
                pre[2][u] = (t >= 1 ? gsm[(8  + u) * 65 + b] : 0.f) + bsm[8  + u];
                pre[3][u] = (t >= 1 ? gsm[(12 + u) * 65 + b] : 0.f) + bsm[12 + u];
            }
            pre[0][0] += xf0.x; pre[0][1] += xf0.y; pre[0][2] += xf0.z; pre[0][3] += xf0.w;
            pre[1][0] += xf1.x; pre[1][1] += xf1.y; pre[1][2] += xf1.z; pre[1][3] += xf1.w;
            pre[2][0] += xf2.x; pre[2][1] += xf2.y; pre[2][2] += xf2.z; pre[2][3] += xf2.w;
            pre[3][0] += xf3.x; pre[3][1] += xf3.y; pre[3][2] += xf3.z; pre[3][3] += xf3.w;
            __nv_bfloat16 hp[4], lp[4];
#pragma unroll
            for (int u = 0; u < 4; ++u) {
                float ig = sigf(pre[0][u]);
                float fg = sigf(pre[1][u]);
                float gg = tanhap(pre[2][u]);
                float og = sigf(pre[3][u]);
                float c  = csm[b * 4 + u];
                c = fg * c + ig * gg;
                csm[b * 4 + u] = c;
                float h = og * tanhap(c);
                hp[u] = __float2bfloat16(h);
                lp[u] = __float2bfloat16(h - __bfloat162float(hp[u]));
            }
            *(uint2*)(g_h1Hi[t & 1] + b * Hx + u0) = *(uint2*)hp;
            *(uint2*)(g_h1Lo[t & 1] + b * Hx + u0) = *(uint2*)lp;
        } else if (tid >= 64 && tid < 128 && l1) {
            const int b = tid - 64;
            float hv[4];
            __nv_bfloat16 hp[4], lp[4];
#pragma unroll
            for (int u = 0; u < 4; ++u) {
                float ig = sigf(gsm[(16 + u) * 65 + b] + bsm[16 + u]);
                float fg = sigf(gsm[(20 + u) * 65 + b] + bsm[20 + u]);
                float gg = tanhap(gsm[(24 + u) * 65 + b] + bsm[24 + u]);
                float og = sigf(gsm[(28 + u) * 65 + b] + bsm[28 + u]);
                float c  = csm[256 + b * 4 + u];
                c = fg * c + ig * gg;
                csm[256 + b * 4 + u] = c;
                hv[u] = og * tanhap(c);
                hp[u] = __float2bfloat16(hv[u]);
                lp[u] = __float2bfloat16(hv[u] - __bfloat162float(hp[u]));
            }
            *(uint2*)(g_h2Hi[(t - 1) & 1] + b * Hx + u0) = *(uint2*)hp;
            *(uint2*)(g_h2Lo[(t - 1) & 1] + b * Hx + u0) = *(uint2*)lp;
            *(float4*)(g_h2C + b * Hx + u0) = make_float4(hv[0], hv[1], hv[2], hv[3]);
        }

        // ---- grid barrier ----------------------------------------------------
        __syncthreads();
        if (tid == 0) {
            __threadfence();
            atomicAdd(bar, 1u);
            unsigned target = 128u * (unsigned)(t + 1);
            while (*((volatile unsigned*)bar) < target) {}
            __threadfence();
        }
        __syncthreads();
    }
}

// ---------------- final FC ---------------------------------------------------
__global__ void fc_kernel(const float* __restrict__ hC, const float* __restrict__ fw,
                          const float* __restrict__ fb, float* __restrict__ out)
{
    __shared__ float hb[Hx];
    int b = blockIdx.x;
    int o = threadIdx.x;
    for (int j = threadIdx.x; j < Hx; j += OUTx) hb[j] = hC[(size_t)b * Hx + j];
    __syncthreads();
    float acc = fb[o];
    const float* wr = fw + (size_t)o * Hx;
#pragma unroll 4
    for (int j = 0; j < Hx; j += 4) {
        float4 w = *(const float4*)(wr + j);
        float4 h = *(const float4*)(hb + j);
        acc += w.x * h.x + w.y * h.y + w.z * h.z + w.w * h.w;
    }
    out[b * OUTx + o] = acc;
}

// ---------------- launch ------------------------------------------------------
extern "C" void kernel_launch(void* const* d_in, const int* in_sizes, int n_in,
                              void* d_out, int out_size)
{
    const float* x    = (const float*)d_in[0];
    const float* Wih0 = (const float*)d_in[1];
    const float* Whh0 = (const float*)d_in[2];
    const float* bih0 = (const float*)d_in[3];
    const float* bhh0 = (const float*)d_in[4];
    const float* Wih1 = (const float*)d_in[5];
    const float* Whh1 = (const float*)d_in[6];
    const float* bih1 = (const float*)d_in[7];
    const float* bhh1 = (const float*)d_in[8];
    const float* fcw  = (const float*)d_in[9];
    const float* fcb  = (const float*)d_in[10];
    float* out = (float*)d_out;

    cudaFuncSetAttribute((const void*)fused_scan,
                         cudaFuncAttributeMaxDynamicSharedMemorySize, FUSED_SMEM);

    void *xg_p, *a2_p, *w2_p, *h2c_p;
    cudaGetSymbolAddress(&xg_p, g_xg);
    cudaGetSymbolAddress(&a2_p, g_A2);
    cudaGetSymbolAddress(&w2_p, g_W2);
    cudaGetSymbolAddress(&h2c_p, g_h2C);

    init_kernel<<<1, 32>>>();

    // layer-0 input projection on tensor cores (split-bf16, 3-pass)
    conv_w_kernel<<<Gx, 128>>>(Wih0, (__nv_bfloat16*)w2_p, Dx);
    conv_a_kernel<<<Sx * Bx, 128>>>(x, (__nv_bfloat16*)a2_p, Dx);
    dim3 mgrid(Gx / 128, (Sx * Bx) / 128);   // (16, 256)
    wmma_gemm_kernel<<<mgrid, 256>>>(
        (const __nv_bfloat16*)a2_p, (const __nv_bfloat16*)w2_p,
        (float*)xg_p, 3 * Dx);

    // balanced fused 2-layer pipelined scan (513 ticks, 128 persistent CTAs)
    fused_scan<<<128, 256, FUSED_SMEM>>>(
        (const float*)xg_p, Whh0, Wih1, Whh1, bih0, bhh0, bih1, bhh1);

    fc_kernel<<<Bx, OUTx>>>((const float*)h2c_p, fcw, fcb, out);
}

// round 13
// speedup vs baseline: 2.5032x; 1.0398x over previous
#include <cuda_runtime.h>
#include <cuda_bf16.h>
#include <mma.h>
#include <cstdint>
#include <cstddef>

using namespace nvcuda;

#define Bx   64
#define Sx   512
#define Dx   256
#define Hx   512
#define Gx   2048   // 4*H
#define OUTx 128
#define HB   (Bx * Hx)   // 32768

// ---------------- scratch (static device allocations are the allowed path) ---
__device__ float g_xg[(size_t)Sx * Bx * Gx];                 // layer-0 gate preacts (no bias)
__device__ __align__(16) __nv_bfloat16 g_h1Hi[2][HB];        // h1 double-buffered hi/lo
__device__ __align__(16) __nv_bfloat16 g_h1Lo[2][HB];
__device__ __align__(16) __nv_bfloat16 g_h2Hi[2][HB];        // h2 double-buffered hi/lo
__device__ __align__(16) __nv_bfloat16 g_h2Lo[2][HB];
__device__ float g_h2C[HB];                                  // h2 fp32 [b][j] for FC
__device__ unsigned g_bar[1];
__device__ __nv_bfloat16 g_A2[(size_t)Sx * Bx * 3 * Dx];     // split-A for gemm0
__device__ __nv_bfloat16 g_W2[(size_t)Gx * 3 * Dx];          // split-W for gemm0

__global__ void init_kernel() { if (threadIdx.x == 0) g_bar[0] = 0u; }

// ---------------- cp.async helpers -------------------------------------------
#define CP16(dst, src) \
    asm volatile("cp.async.cg.shared.global [%0], [%1], 16;" :: "r"(dst), "l"(src))
#define CP_COMMIT() asm volatile("cp.async.commit_group;" ::: "memory")
#define CP_WAIT0()  asm volatile("cp.async.wait_group 0;" ::: "memory")
#define CP_WAIT1()  asm volatile("cp.async.wait_group 1;" ::: "memory")

// ---------------- fp32 -> (hi,lo) bf16 split conversions ---------------------
__global__ void conv_w_kernel(const float* __restrict__ W, __nv_bfloat16* __restrict__ W2, int K)
{
    int n = blockIdx.x;
    const float* src = W + (size_t)n * K;
    __nv_bfloat16* dst = W2 + (size_t)n * 3 * K;
    for (int k = threadIdx.x; k < K; k += blockDim.x) {
        float v = src[k];
        __nv_bfloat16 hi = __float2bfloat16(v);
        __nv_bfloat16 lo = __float2bfloat16(v - __bfloat162float(hi));
        dst[k] = hi; dst[K + k] = lo; dst[2 * K + k] = hi;
    }
}

__global__ void conv_a_kernel(const float* __restrict__ A, __nv_bfloat16* __restrict__ A2, int K)
{
    int m = blockIdx.x;   // m = s*64 + b ; A is x[b][s][k]
    const float* src = A + (size_t)(m & 63) * (Sx * Dx) + (size_t)(m >> 6) * Dx;
    __nv_bfloat16* dst = A2 + (size_t)m * 3 * K;
    for (int k = threadIdx.x; k < K; k += blockDim.x) {
        float v = src[k];
        __nv_bfloat16 hi = __float2bfloat16(v);
        __nv_bfloat16 lo = __float2bfloat16(v - __bfloat162float(hi));
        dst[k] = hi; dst[K + k] = hi; dst[2 * K + k] = lo;
    }
}

// ---------------- HMMA (wmma) GEMM for layer-0 input projection ---------------
// cp.async double-buffered; <=128 regs so 2 CTAs/SM.
#define LDP 40

__global__ void __launch_bounds__(256, 2) wmma_gemm_kernel(
    const __nv_bfloat16* __restrict__ A2, const __nv_bfloat16* __restrict__ W2,
    float* __restrict__ C, int Ktot)
{
    __shared__ __align__(16) __nv_bfloat16 As[2][128 * LDP];
    __shared__ __align__(16) __nv_bfloat16 Bs[2][128 * LDP];

    const int tid = threadIdx.x;
    const int wid = tid >> 5;
    const int m0 = blockIdx.y * 128;
    const int n0 = blockIdx.x * 128;
    const int wm = (wid >> 2) * 64;
    const int wn = (wid & 3) * 32;

    wmma::fragment<wmma::accumulator, 16, 16, 16, float> acc[4][2];
#pragma unroll
    for (int i = 0; i < 4; ++i)
#pragma unroll
        for (int j = 0; j < 2; ++j) wmma::fill_fragment(acc[i][j], 0.f);

    const int ca = tid, cb = tid + 256;
    const int ra = ca >> 2, qa = ca & 3;
    const int rb = cb >> 2, qb = cb & 3;
    const char* Ag = (const char*)A2;
    const char* Bg = (const char*)W2;
    const size_t aoff0 = ((size_t)(m0 + ra) * Ktot + qa * 8) * 2;
    const size_t aoff1 = ((size_t)(m0 + rb) * Ktot + qb * 8) * 2;
    const size_t boff0 = ((size_t)(n0 + ra) * Ktot + qa * 8) * 2;
    const size_t boff1 = ((size_t)(n0 + rb) * Ktot + qb * 8) * 2;
    const int s0 = ra * (LDP * 2) + qa * 16;
    const int s1 = rb * (LDP * 2) + qb * 16;

    uint32_t sA[2], sB[2];
    sA[0] = (uint32_t)__cvta_generic_to_shared(As[0]);
    sA[1] = (uint32_t)__cvta_generic_to_shared(As[1]);
    sB[0] = (uint32_t)__cvta_generic_to_shared(Bs[0]);
    sB[1] = (uint32_t)__cvta_generic_to_shared(Bs[1]);

    const int T = Ktot >> 5;
    // prologue: tile 0 -> buf 0
    {
        CP16(sA[0] + s0, Ag + aoff0);
        CP16(sA[0] + s1, Ag + aoff1);
        CP16(sB[0] + s0, Bg + boff0);
        CP16(sB[0] + s1, Bg + boff1);
        CP_COMMIT();
    }

    for (int t = 0; t < T; ++t) {
        const int buf = t & 1;
        const bool more = (t + 1 < T);
        if (more) {
            size_t ko = (size_t)(t + 1) * 64;
            const int nb = buf ^ 1;
            CP16(sA[nb] + s0, Ag + aoff0 + ko);
            CP16(sA[nb] + s1, Ag + aoff1 + ko);
            CP16(sB[nb] + s0, Bg + boff0 + ko);
            CP16(sB[nb] + s1, Bg + boff1 + ko);
            CP_COMMIT();
            CP_WAIT1();
        } else {
            CP_WAIT0();
        }
        __syncthreads();
#pragma unroll
        for (int ks = 0; ks < 2; ++ks) {
            wmma::fragment<wmma::matrix_a, 16, 16, 16, __nv_bfloat16, wmma::row_major> af[4];
            wmma::fragment<wmma::matrix_b, 16, 16, 16, __nv_bfloat16, wmma::col_major> bf[2];
#pragma unroll
            for (int i = 0; i < 4; ++i)
                wmma::load_matrix_sync(af[i], &As[buf][(wm + i * 16) * LDP + ks * 16], LDP);
#pragma unroll
            for (int j = 0; j < 2; ++j)
                wmma::load_matrix_sync(bf[j], &Bs[buf][(wn + j * 16) * LDP + ks * 16], LDP);
#pragma unroll
            for (int i = 0; i < 4; ++i)
#pragma unroll
                for (int j = 0; j < 2; ++j)
                    wmma::mma_sync(acc[i][j], af[i], bf[j], acc[i][j]);
        }
        __syncthreads();
    }

#pragma unroll
    for (int i = 0; i < 4; ++i)
#pragma unroll
        for (int j = 0; j < 2; ++j)
            wmma::store_matrix_sync(
                C + (size_t)(m0 + wm + i * 16) * Gx + n0 + wn + j * 16,
                acc[i][j], Gx, wmma::mem_row_major);
}

// ---------------- balanced fused 2-layer pipelined LSTM scan ------------------
// 128 identical CTAs; each owns 4 hidden units of BOTH layers. Tick t: L0 step t,
// L1 step t-1. cp.async 4-phase pipeline overlaps tile staging with mma.
#define PWE    520
#define SM_AHI 0
#define SM_ALO 66560
#define SM_WLO 133120                  // [3][16][520] bf16 W-lo tiles (resident)
#define SM_GSM 183040                  // [32][65] floats
#define SM_CSM 191360                  // [2][64][4] floats
#define SM_BSM 193408                  // [32] floats
#define FUSED_SMEM 193664

typedef wmma::fragment<wmma::matrix_a, 16, 16, 16, __nv_bfloat16, wmma::row_major> frag_a;
typedef wmma::fragment<wmma::matrix_b, 16, 16, 16, __nv_bfloat16, wmma::col_major> frag_b;
typedef wmma::fragment<wmma::accumulator, 16, 16, 16, float> frag_c;

__device__ __forceinline__ float tanhap(float x) {
    float y; asm("tanh.approx.f32 %0, %1;" : "=f"(y) : "f"(x)); return y;
}
__device__ __forceinline__ float sigf(float x) {
    return fmaf(tanhap(x * 0.5f), 0.5f, 0.5f);
}

// issue async stage of 64x512 bf16 [b][j] tile into padded smem (1040B rows)
__device__ __forceinline__ void stage_issue(uint32_t dstb, const __nv_bfloat16* src, int tid) {
#pragma unroll
    for (int i = 0; i < 16; ++i) {
        int c = tid + i * 256;
        int row = c >> 6, col = c & 63;
        CP16(dstb + row * 1040 + col * 16, src + row * Hx + col * 8);
    }
    CP_COMMIT();
}

__global__ void __launch_bounds__(256, 1) fused_scan(
    const float* __restrict__ xg,
    const float* __restrict__ Whh0, const float* __restrict__ Wih1,
    const float* __restrict__ Whh1,
    const float* __restrict__ bih0, const float* __restrict__ bhh0,
    const float* __restrict__ bih1, const float* __restrict__ bhh1)
{
    extern __shared__ char sm[];
    __nv_bfloat16* AsmHi = (__nv_bfloat16*)(sm + SM_AHI);
    __nv_bfloat16* AsmLo = (__nv_bfloat16*)(sm + SM_ALO);
    __nv_bfloat16* WloS  = (__nv_bfloat16*)(sm + SM_WLO);
    float* gsm = (float*)(sm + SM_GSM);
    float* csm = (float*)(sm + SM_CSM);
    float* bsm = (float*)(sm + SM_BSM);
    float* P   = (float*)(sm + SM_AHI);            // partials alias A region
    const uint32_t sHi = (uint32_t)__cvta_generic_to_shared(AsmHi);
    const uint32_t sLo = (uint32_t)__cvta_generic_to_shared(AsmLo);

    const int tid = threadIdx.x;
    const int wid = tid >> 5;
    const int kb  = wid * 64;
    const int u0  = blockIdx.x * 4;
    unsigned* bar = g_bar;

    // ---- prologue: split 3 W matrices; hi-frags resident, lo tiles in smem ---
    frag_b whi[3][4];
    const float* Wsrcs[3] = {Whh0, Wih1, Whh1};
#pragma unroll
    for (int m = 0; m < 3; ++m) {
        const float* Wsrc = Wsrcs[m];
        __nv_bfloat16* loT = WloS + m * 16 * PWE;
#pragma unroll 4
        for (int i = 0; i < 32; ++i) {
            int idx = tid + i * 256;               // 16 rows x 512 k
            int r = idx >> 9, k = idx & 511;
            float v = Wsrc[(size_t)((r >> 2) * Hx + u0 + (r & 3)) * Hx + k];
            __nv_bfloat16 hi = __float2bfloat16(v);
            AsmHi[r * PWE + k] = hi;
            loT[r * PWE + k] = __float2bfloat16(v - __bfloat162float(hi));
        }
        __syncthreads();
#pragma unroll
        for (int j = 0; j < 4; ++j)
            wmma::load_matrix_sync(whi[m][j], AsmHi + kb + j * 16, PWE);
        __syncthreads();
    }
    if (tid < 32) {
        int g = (tid >> 2) & 3, u = tid & 3;
        bsm[tid] = (tid < 16)
            ? (bih0[g * Hx + u0 + u] + bhh0[g * Hx + u0 + u])
            : (bih1[g * Hx + u0 + u] + bhh1[g * Hx + u0 + u]);
    }
    if (tid < 128) {
#pragma unroll
        for (int u = 0; u < 4; ++u) csm[tid * 4 + u] = 0.f;  // [2][64][4] flat
    }
    __syncthreads();

    // ---- main pipeline loop: 513 ticks ---------------------------------------
    for (int t = 0; t <= Sx; ++t) {
        const bool l0   = (t < Sx);
        const bool hasA = (t >= 1);
        const bool hasB = (t >= 2);

        // prefetch xg for L0 gate threads
        float4 xf0, xf1, xf2, xf3;
        if (l0 && tid < 64) {
            const float* xp = xg + ((size_t)(t * Bx + tid)) * Gx + u0;
            xf0 = __ldcg((const float4*)(xp));
            xf1 = __ldcg((const float4*)(xp + Hx));
            xf2 = __ldcg((const float4*)(xp + 2 * Hx));
            xf3 = __ldcg((const float4*)(xp + 3 * Hx));
        }

        frag_c aL0[4], aL1[4];
#pragma unroll
        for (int mt = 0; mt < 4; ++mt) {
            wmma::fill_fragment(aL0[mt], 0.f);
            wmma::fill_fragment(aL1[mt], 0.f);
        }

        if (hasA) {
            // issue h1[t-1] hi+lo
            stage_issue(sHi, g_h1Hi[(t - 1) & 1], tid);    // g1
            stage_issue(sLo, g_h1Lo[(t - 1) & 1], tid);    // g2
            CP_WAIT1(); __syncthreads();                   // hi(A) ready

            // ---- HI-A passes: ah x {whi0, wlo0, whi1, wlo1} -------------------
#pragma unroll
            for (int j = 0; j < 4; ++j) {
                frag_a ah[4];
#pragma unroll
                for (int mt = 0; mt < 4; ++mt)
                    wmma::load_matrix_sync(ah[mt], AsmHi + mt * 16 * PWE + kb + j * 16, PWE);
                if (l0) {
#pragma unroll
                    for (int mt = 0; mt < 4; ++mt)
                        wmma::mma_sync(aL0[mt], ah[mt], whi[0][j], aL0[mt]);
                    frag_b wl0;
                    wmma::load_matrix_sync(wl0, WloS + 0 * 16 * PWE + kb + j * 16, PWE);
#pragma unroll
                    for (int mt = 0; mt < 4; ++mt)
                        wmma::mma_sync(aL0[mt], ah[mt], wl0, aL0[mt]);
                }
#pragma unroll
                for (int mt = 0; mt < 4; ++mt)
                    wmma::mma_sync(aL1[mt], ah[mt], whi[1][j], aL1[mt]);
                frag_b wl1;
                wmma::load_matrix_sync(wl1, WloS + 1 * 16 * PWE + kb + j * 16, PWE);
#pragma unroll
                for (int mt = 0; mt < 4; ++mt)
                    wmma::mma_sync(aL1[mt], ah[mt], wl1, aL1[mt]);
            }
            __syncthreads();                               // done reading AHi

            // overlap: bring h2hi[t-2] into the freed hi buffer
            if (hasB) { stage_issue(sHi, g_h2Hi[t & 1], tid); CP_WAIT1(); }
            else      { CP_WAIT0(); }
            __syncthreads();                               // lo(A) ready

            // ---- LO-A pass: al x {whi0, whi1} --------------------------------
#pragma unroll
            for (int j = 0; j < 4; ++j) {
                frag_a al[4];
#pragma unroll
                for (int mt = 0; mt < 4; ++mt)
                    wmma::load_matrix_sync(al[mt], AsmLo + mt * 16 * PWE + kb + j * 16, PWE);
                if (l0) {
#pragma unroll
                    for (int mt = 0; mt < 4; ++mt)
                        wmma::mma_sync(aL0[mt], al[mt], whi[0][j], aL0[mt]);
                }
#pragma unroll
                for (int mt = 0; mt < 4; ++mt)
                    wmma::mma_sync(aL1[mt], al[mt], whi[1][j], aL1[mt]);
            }
            __syncthreads();                               // done reading ALo

            if (hasB) {
                stage_issue(sLo, g_h2Lo[t & 1], tid);      // lo(B) into freed lo buffer
                CP_WAIT1(); __syncthreads();               // hi(B) ready

                // ---- HI-B passes: ah x {whi2, wlo2} ---------------------------
#pragma unroll
                for (int j = 0; j < 4; ++j) {
                    frag_a ah[4];
#pragma unroll
                    for (int mt = 0; mt < 4; ++mt)
                        wmma::load_matrix_sync(ah[mt], AsmHi + mt * 16 * PWE + kb + j * 16, PWE);
#pragma unroll
                    for (int mt = 0; mt < 4; ++mt)
                        wmma::mma_sync(aL1[mt], ah[mt], whi[2][j], aL1[mt]);
                    frag_b wl2;
                    wmma::load_matrix_sync(wl2, WloS + 2 * 16 * PWE + kb + j * 16, PWE);
#pragma unroll
                    for (int mt = 0; mt < 4; ++mt)
                        wmma::mma_sync(aL1[mt], ah[mt], wl2, aL1[mt]);
                }
                CP_WAIT0(); __syncthreads();               // lo(B) ready (+ done AHi)

                // ---- LO-B pass: al x whi2 -------------------------------------
#pragma unroll
                for (int j = 0; j < 4; ++j) {
                    frag_a al[4];
#pragma unroll
                    for (int mt = 0; mt < 4; ++mt)
                        wmma::load_matrix_sync(al[mt], AsmLo + mt * 16 * PWE + kb + j * 16, PWE);
#pragma unroll
                    for (int mt = 0; mt < 4; ++mt)
                        wmma::mma_sync(aL1[mt], al[mt], whi[2][j], aL1[mt]);
                }
                __syncthreads();                           // done reading ALo
            }

            // ---- partial store + 8-way reduce --------------------------------
#pragma unroll
            for (int mt = 0; mt < 4; ++mt) {
                wmma::store_matrix_sync(P + wid * 2304 + mt * 16 * 36, aL0[mt],
                                        36, wmma::mem_row_major);
                wmma::store_matrix_sync(P + wid * 2304 + mt * 16 * 36 + 16, aL1[mt],
                                        36, wmma::mem_row_major);
            }
            __syncthreads();
#pragma unroll
            for (int i = 0; i < 8; ++i) {
                int cell = tid + i * 256;
                int b = cell >> 5, r = cell & 31;
                float v = 0.f;
#pragma unroll
                for (int w = 0; w < 8; ++w) v += P[w * 2304 + b * 36 + r];
                gsm[r * 65 + b] = v;
            }
            __syncthreads();
        }

        // ---- gates: tid<64 -> L0 batch b, 64..127 -> L1 batch b-64 ----------
        if (tid < 64 && l0) {
            const int b = tid;
            float pre[4][4];
#pragma unroll
            for (int u = 0; u < 4; ++u) {
                pre[0][u] = (hasA ? gsm[(0  + u) * 65 + b] : 0.f) + bsm[0  + u];
                pre[1][u] = (hasA ? gsm[(4  + u) * 65 + b] : 0.f) + bsm[4  + u];
                pre[2][u] = (hasA ? gsm[(8  + u) * 65 + b] : 0.f) + bsm[8  + u];
                pre[3][u] = (hasA ? gsm[(12 + u) * 65 + b] : 0.f) + bsm[12 + u];
            }
            pre[0][0] += xf0.x; pre[0][1] += xf0.y; pre[0][2] += xf0.z; pre[0][3] += xf0.w;
            pre[1][0] += xf1.x; pre[1][1] += xf1.y; pre[1][2] += xf1.z; pre[1][3] += xf1.w;
            pre[2][0] += xf2.x; pre[2][1] += xf2.y; pre[2][2] += xf2.z; pre[2][3] += xf2.w;
            pre[3][0] += xf3.x; pre[3][1] += xf3.y; pre[3][2] += xf3.z; pre[3][3] += xf3.w;
            __nv_bfloat16 hp[4], lp[4];
#pragma unroll
            for (int u = 0; u < 4; ++u) {
                float ig = sigf(pre[0][u]);
                float fg = sigf(pre[1][u]);
                float gg = tanhap(pre[2][u]);
                float og = sigf(pre[3][u]);
                float c  = csm[b * 4 + u];
                c = fg * c + ig * gg;
                csm[b * 4 + u] = c;
                float h = og * tanhap(c);
                hp[u] = __float2bfloat16(h);
                lp[u] = __float2bfloat16(h - __bfloat162float(hp[u]));
            }
            *(uint2*)(g_h1Hi[t & 1] + b * Hx + u0) = *(uint2*)hp;
            *(uint2*)(g_h1Lo[t & 1] + b * Hx + u0) = *(uint2*)lp;
        } else if (tid >= 64 && tid < 128 && hasA) {
            const int b = tid - 64;
            float hv[4];
            __nv_bfloat16 hp[4], lp[4];
#pragma unroll
            for (int u = 0; u < 4; ++u) {
                float ig = sigf(gsm[(16 + u) * 65 + b] + bsm[16 + u]);
                float fg = sigf(gsm[(20 + u) * 65 + b] + bsm[20 + u]);
                float gg = tanhap(gsm[(24 + u) * 65 + b] + bsm[24 + u]);
                float og = sigf(gsm[(28 + u) * 65 + b] + bsm[28 + u]);
                float c  = csm[256 + b * 4 + u];
                c = fg * c + ig * gg;
                csm[256 + b * 4 + u] = c;
                hv[u] = og * tanhap(c);
                hp[u] = __float2bfloat16(hv[u]);
                lp[u] = __float2bfloat16(hv[u] - __bfloat162float(hp[u]));
            }
            *(uint2*)(g_h2Hi[(t - 1) & 1] + b * Hx + u0) = *(uint2*)hp;
            *(uint2*)(g_h2Lo[(t - 1) & 1] + b * Hx + u0) = *(uint2*)lp;
            *(float4*)(g_h2C + b * Hx + u0) = make_float4(hv[0], hv[1], hv[2], hv[3]);
        }

        // ---- grid barrier ----------------------------------------------------
        __syncthreads();
        if (tid == 0) {
            __threadfence();
            atomicAdd(bar, 1u);
            unsigned target = 128u * (unsigned)(t + 1);
            while (*((volatile unsigned*)bar) < target) {}
            __threadfence();
        }
        __syncthreads();
    }
}

// ---------------- final FC ---------------------------------------------------
__global__ void fc_kernel(const float* __restrict__ hC, const float* __restrict__ fw,
                          const float* __restrict__ fb, float* __restrict__ out)
{
    __shared__ float hb[Hx];
    int b = blockIdx.x;
    int o = threadIdx.x;
    for (int j = threadIdx.x; j < Hx; j += OUTx) hb[j] = hC[(size_t)b * Hx + j];
    __syncthreads();
    float acc = fb[o];
    const float* wr = fw + (size_t)o * Hx;
#pragma unroll 4
    for (int j = 0; j < Hx; j += 4) {
        float4 w = *(const float4*)(wr + j);
        float4 h = *(const float4*)(hb + j);
        acc += w.x * h.x + w.y * h.y + w.z * h.z + w.w * h.w;
    }
    out[b * OUTx + o] = acc;
}

// ---------------- launch ------------------------------------------------------
extern "C" void kernel_launch(void* const* d_in, const int* in_sizes, int n_in,
                              void* d_out, int out_size)
{
    const float* x    = (const float*)d_in[0];
    const float* Wih0 = (const float*)d_in[1];
    const float* Whh0 = (const float*)d_in[2];
    const float* bih0 = (const float*)d_in[3];
    const float* bhh0 = (const float*)d_in[4];
    const float* Wih1 = (const float*)d_in[5];
    const float* Whh1 = (const float*)d_in[6];
    const float* bih1 = (const float*)d_in[7];
    const float* bhh1 = (const float*)d_in[8];
    const float* fcw  = (const float*)d_in[9];
    const float* fcb  = (const float*)d_in[10];
    float* out = (float*)d_out;

    cudaFuncSetAttribute((const void*)fused_scan,
                         cudaFuncAttributeMaxDynamicSharedMemorySize, FUSED_SMEM);

    void *xg_p, *a2_p, *w2_p, *h2c_p;
    cudaGetSymbolAddress(&xg_p, g_xg);
    cudaGetSymbolAddress(&a2_p, g_A2);
    cudaGetSymbolAddress(&w2_p, g_W2);
    cudaGetSymbolAddress(&h2c_p, g_h2C);

    init_kernel<<<1, 32>>>();

    // layer-0 input projection on tensor cores (split-bf16, 3-pass)
    conv_w_kernel<<<Gx, 128>>>(Wih0, (__nv_bfloat16*)w2_p, Dx);
    conv_a_kernel<<<Sx * Bx, 128>>>(x, (__nv_bfloat16*)a2_p, Dx);
    dim3 mgrid(Gx / 128, (Sx * Bx) / 128);   // (16, 256)
    wmma_gemm_kernel<<<mgrid, 256>>>(
        (const __nv_bfloat16*)a2_p, (const __nv_bfloat16*)w2_p,
        (float*)xg_p, 3 * Dx);

    // balanced fused 2-layer pipelined scan (513 ticks, 128 persistent CTAs)
    fused_scan<<<128, 256, FUSED_SMEM>>>(
        (const float*)xg_p, Whh0, Wih1, Whh1, bih0, bhh0, bih1, bhh1);

    fc_kernel<<<Bx, OUTx>>>((const float*)h2c_p, fcw, fcb, out);
}